// round 1
// baseline (speedup 1.0000x reference)
#include <cuda_runtime.h>
#include <math.h>

// Problem constants
constexpr int Bz = 4;          // batch
constexpr int Sq = 2048;       // sequence
constexpr int Dm = 1024;       // d_model
constexpr int Hh = 16;         // heads
constexpr int Dh = 64;         // head dim
constexpr int Mr = Bz * Sq;    // 8192 rows

// GEMM tiling
constexpr int BM = 128, BN = 128, BK = 16;

// Flash tiling
constexpr int FT = 64;

// Scratch (allocation-free rule: __device__ globals)
__device__ float g_Q[(size_t)Mr * Dm];
__device__ float g_K[(size_t)Mr * Dm];
__device__ float g_V[(size_t)Mr * Dm];
__device__ float g_AO[(size_t)Mr * Dm];

// ---------------------------------------------------------------------------
// C[M,N] = A[M,K] * W[N,K]^T + bias[N]
// scatter=0: C row-major [M, N]
// scatter=1: C is [b, h, s, d] with b=m/Sq, s=m%Sq, h=n/Dh, d=n%Dh
// ---------------------------------------------------------------------------
__global__ __launch_bounds__(256, 2)
void sgemm_nt(const float* __restrict__ A, const float* __restrict__ W,
              const float* __restrict__ bias, float* __restrict__ C,
              const int scatter)
{
    __shared__ float As[BK][BM];
    __shared__ float Bs[BK][BN];
    const int tid = threadIdx.x;
    const int bm = blockIdx.y * BM;
    const int bn = blockIdx.x * BN;
    const int ty = tid >> 4;    // 0..15
    const int tx = tid & 15;    // 0..15

    float acc[8][8];
    #pragma unroll
    for (int r = 0; r < 8; r++)
        #pragma unroll
        for (int c = 0; c < 8; c++) acc[r][c] = 0.f;

    for (int k0 = 0; k0 < Dm; k0 += BK) {
        // Load 128x16 tiles of A and W (both K-contiguous), store transposed.
        #pragma unroll
        for (int l = 0; l < 2; l++) {
            int f = tid + l * 256;          // 0..511 float4 index
            int row = f >> 2;               // 0..127
            int c4 = (f & 3) << 2;          // 0,4,8,12
            float4 va = *reinterpret_cast<const float4*>(
                &A[(size_t)(bm + row) * Dm + k0 + c4]);
            As[c4 + 0][row] = va.x; As[c4 + 1][row] = va.y;
            As[c4 + 2][row] = va.z; As[c4 + 3][row] = va.w;
            float4 vb = *reinterpret_cast<const float4*>(
                &W[(size_t)(bn + row) * Dm + k0 + c4]);
            Bs[c4 + 0][row] = vb.x; Bs[c4 + 1][row] = vb.y;
            Bs[c4 + 2][row] = vb.z; Bs[c4 + 3][row] = vb.w;
        }
        __syncthreads();
        #pragma unroll
        for (int kk = 0; kk < BK; kk++) {
            float4 a0 = *reinterpret_cast<const float4*>(&As[kk][ty * 8]);
            float4 a1 = *reinterpret_cast<const float4*>(&As[kk][ty * 8 + 4]);
            float4 b0 = *reinterpret_cast<const float4*>(&Bs[kk][tx * 8]);
            float4 b1 = *reinterpret_cast<const float4*>(&Bs[kk][tx * 8 + 4]);
            float a[8] = {a0.x, a0.y, a0.z, a0.w, a1.x, a1.y, a1.z, a1.w};
            float b[8] = {b0.x, b0.y, b0.z, b0.w, b1.x, b1.y, b1.z, b1.w};
            #pragma unroll
            for (int r = 0; r < 8; r++)
                #pragma unroll
                for (int c = 0; c < 8; c++)
                    acc[r][c] = fmaf(a[r], b[c], acc[r][c]);
        }
        __syncthreads();
    }

    #pragma unroll
    for (int r = 0; r < 8; r++) {
        const int m = bm + ty * 8 + r;
        #pragma unroll
        for (int c = 0; c < 8; c++) {
            const int n = bn + tx * 8 + c;
            const float v = acc[r][c] + bias[n];
            if (scatter == 0) {
                C[(size_t)m * Dm + n] = v;
            } else {
                const int b = m >> 11;          // m / 2048
                const int s = m & 2047;
                const int h = n >> 6;           // n / 64
                const int d = n & 63;
                C[((((size_t)b * Hh + h) * Sq + s) << 6) + d] = v;
            }
        }
    }
}

// ---------------------------------------------------------------------------
// Flash attention, fp32, causal. One block = one (b*h, q-tile of 64 rows).
// Q,K,V in [b,h,s,d] layout. Output written in [b, s, h*64+d] layout.
// ---------------------------------------------------------------------------
constexpr int KVS = Dh + 1;   // padded stride for K/V tile (bank conflicts)
constexpr int SPS = FT + 1;   // padded stride for score tile
constexpr int FLASH_SMEM_FLOATS = FT * Dh + FT * KVS + FT * SPS + 3 * FT;
constexpr int FLASH_SMEM_BYTES = FLASH_SMEM_FLOATS * 4;

__global__ __launch_bounds__(256)
void flash_attn(const float* __restrict__ Q, const float* __restrict__ K,
                const float* __restrict__ V, float* __restrict__ AO)
{
    extern __shared__ float smem[];
    float* Qs = smem;                       // [FT][Dh]   (no pad needed: broadcast reads)
    float* KVs = Qs + FT * Dh;              // [FT][KVS]  K tile then V tile
    float* SP = KVs + FT * KVS;             // [FT][SPS]
    float* row_m = SP + FT * SPS;           // [FT]
    float* row_l = row_m + FT;              // [FT]
    float* row_r = row_l + FT;              // [FT]

    const int bh = blockIdx.y;              // 0..63  (= b*Hh + h)
    const int qt = blockIdx.x;              // 0..31
    const int q0 = qt * FT;
    const int tid = threadIdx.x;
    const int ty = tid >> 4;                // 0..15 -> 4 q-rows each
    const int tx = tid & 15;                // 0..15 -> 4 d-cols each

    const float* Qb = Q + (size_t)bh * Sq * Dh;
    const float* Kb = K + (size_t)bh * Sq * Dh;
    const float* Vb = V + (size_t)bh * Sq * Dh;

    // Load Q tile (64x64 floats = 1024 float4, 4 per thread)
    #pragma unroll
    for (int l = 0; l < 4; l++) {
        int f = tid + l * 256;
        int row = f >> 4;
        int c4 = (f & 15) << 2;
        float4 v = *reinterpret_cast<const float4*>(&Qb[(size_t)(q0 + row) * Dh + c4]);
        Qs[row * Dh + c4 + 0] = v.x; Qs[row * Dh + c4 + 1] = v.y;
        Qs[row * Dh + c4 + 2] = v.z; Qs[row * Dh + c4 + 3] = v.w;
    }
    if (tid < FT) { row_m[tid] = -1e30f; row_l[tid] = 0.f; }

    float o[4][4];
    #pragma unroll
    for (int r = 0; r < 4; r++)
        #pragma unroll
        for (int c = 0; c < 4; c++) o[r][c] = 0.f;

    __syncthreads();

    for (int kt = 0; kt <= qt; kt++) {
        const int k0 = kt * FT;
        // Load K tile into KVs
        #pragma unroll
        for (int l = 0; l < 4; l++) {
            int f = tid + l * 256;
            int row = f >> 4;
            int c4 = (f & 15) << 2;
            float4 v = *reinterpret_cast<const float4*>(&Kb[(size_t)(k0 + row) * Dh + c4]);
            KVs[row * KVS + c4 + 0] = v.x; KVs[row * KVS + c4 + 1] = v.y;
            KVs[row * KVS + c4 + 2] = v.z; KVs[row * KVS + c4 + 3] = v.w;
        }
        __syncthreads();

        // S = (Q K^T) * 1/sqrt(Dh); micro-tile 4x4 per thread
        float s[4][4];
        #pragma unroll
        for (int r = 0; r < 4; r++)
            #pragma unroll
            for (int c = 0; c < 4; c++) s[r][c] = 0.f;

        #pragma unroll 8
        for (int d = 0; d < Dh; d++) {
            float a[4], b[4];
            #pragma unroll
            for (int r = 0; r < 4; r++) a[r] = Qs[(ty * 4 + r) * Dh + d];
            #pragma unroll
            for (int c = 0; c < 4; c++) b[c] = KVs[(tx * 4 + c) * KVS + d];
            #pragma unroll
            for (int r = 0; r < 4; r++)
                #pragma unroll
                for (int c = 0; c < 4; c++)
                    s[r][c] = fmaf(a[r], b[c], s[r][c]);
        }

        const bool diag = (kt == qt);
        #pragma unroll
        for (int r = 0; r < 4; r++) {
            const int i = ty * 4 + r;
            #pragma unroll
            for (int c = 0; c < 4; c++) {
                const int j = tx * 4 + c;
                float v = s[r][c] * 0.125f;     // 1/sqrt(64)
                if (diag && j > i) v = -1e30f;  // causal mask (k0==q0 on diagonal)
                SP[i * SPS + j] = v;
            }
        }
        __syncthreads();

        // Load V tile into KVs (K no longer needed)
        #pragma unroll
        for (int l = 0; l < 4; l++) {
            int f = tid + l * 256;
            int row = f >> 4;
            int c4 = (f & 15) << 2;
            float4 v = *reinterpret_cast<const float4*>(&Vb[(size_t)(k0 + row) * Dh + c4]);
            KVs[row * KVS + c4 + 0] = v.x; KVs[row * KVS + c4 + 1] = v.y;
            KVs[row * KVS + c4 + 2] = v.z; KVs[row * KVS + c4 + 3] = v.w;
        }

        // Online softmax stats: one thread per q row
        if (tid < FT) {
            const int i = tid;
            const float m_old = row_m[i];
            float mx = m_old;
            #pragma unroll 8
            for (int j = 0; j < FT; j++) mx = fmaxf(mx, SP[i * SPS + j]);
            const float rf = __expf(m_old - mx);
            float sum = 0.f;
            #pragma unroll 8
            for (int j = 0; j < FT; j++) {
                const float p = __expf(SP[i * SPS + j] - mx);
                SP[i * SPS + j] = p;
                sum += p;
            }
            row_l[i] = row_l[i] * rf + sum;
            row_m[i] = mx;
            row_r[i] = rf;
        }
        __syncthreads();

        // Rescale O and accumulate O += P * V
        float rr[4];
        #pragma unroll
        for (int r = 0; r < 4; r++) rr[r] = row_r[ty * 4 + r];
        #pragma unroll
        for (int r = 0; r < 4; r++)
            #pragma unroll
            for (int c = 0; c < 4; c++) o[r][c] *= rr[r];

        #pragma unroll 8
        for (int j = 0; j < FT; j++) {
            float p[4], v[4];
            #pragma unroll
            for (int r = 0; r < 4; r++) p[r] = SP[(ty * 4 + r) * SPS + j];
            #pragma unroll
            for (int c = 0; c < 4; c++) v[c] = KVs[j * KVS + tx * 4 + c];
            #pragma unroll
            for (int r = 0; r < 4; r++)
                #pragma unroll
                for (int c = 0; c < 4; c++)
                    o[r][c] = fmaf(p[r], v[c], o[r][c]);
        }
        __syncthreads();   // protect KVs/SP before next iteration
    }

    // Finalize and write to [b, s, h*64+d]
    const int b = bh / Hh;
    const int h = bh % Hh;
    #pragma unroll
    for (int r = 0; r < 4; r++) {
        const int i = ty * 4 + r;
        const float inv = 1.0f / row_l[i];
        const int srow = q0 + i;
        #pragma unroll
        for (int c = 0; c < 4; c++) {
            const int d = tx * 4 + c;
            AO[((size_t)b * Sq + srow) * Dm + h * Dh + d] = o[r][c] * inv;
        }
    }
}

// ---------------------------------------------------------------------------
// Input order (metadata): x, mask, Wq, bq, Wk, bk, Wv, bv, Wo, bo
// ---------------------------------------------------------------------------
extern "C" void kernel_launch(void* const* d_in, const int* in_sizes, int n_in,
                              void* d_out, int out_size)
{
    const float* x  = (const float*)d_in[0];
    // d_in[1] = mask (causal, known statically) — unused
    const float* Wq = (const float*)d_in[2];
    const float* bq = (const float*)d_in[3];
    const float* Wk = (const float*)d_in[4];
    const float* bk = (const float*)d_in[5];
    const float* Wv = (const float*)d_in[6];
    const float* bv = (const float*)d_in[7];
    const float* Wo = (const float*)d_in[8];
    const float* bo = (const float*)d_in[9];
    float* out = (float*)d_out;

    float *gQ, *gK, *gV, *gAO;
    cudaGetSymbolAddress((void**)&gQ, g_Q);
    cudaGetSymbolAddress((void**)&gK, g_K);
    cudaGetSymbolAddress((void**)&gV, g_V);
    cudaGetSymbolAddress((void**)&gAO, g_AO);

    static bool attr_set = false;
    if (!attr_set) {
        cudaFuncSetAttribute(flash_attn,
                             cudaFuncAttributeMaxDynamicSharedMemorySize,
                             FLASH_SMEM_BYTES);
        attr_set = true;
    }

    const dim3 ggrid(Dm / BN, Mr / BM);   // (8, 64)
    sgemm_nt<<<ggrid, 256>>>(x, Wq, bq, gQ, 1);
    sgemm_nt<<<ggrid, 256>>>(x, Wk, bk, gK, 1);
    sgemm_nt<<<ggrid, 256>>>(x, Wv, bv, gV, 1);

    flash_attn<<<dim3(Sq / FT, Bz * Hh), 256, FLASH_SMEM_BYTES>>>(gQ, gK, gV, gAO);

    sgemm_nt<<<ggrid, 256>>>(gAO, Wo, bo, out, 0);
}

// round 3
// speedup vs baseline: 1.5957x; 1.5957x over previous
#include <cuda_runtime.h>
#include <cuda_bf16.h>
#include <cstdint>
#include <math.h>

// Problem constants
constexpr int Bz = 4;
constexpr int Sq = 2048;
constexpr int Dm = 1024;
constexpr int Hh = 16;
constexpr int Dh = 64;
constexpr int Mr = Bz * Sq;    // 8192

// Flash tiling
constexpr int FT = 64;

// Scratch (allocation-free rule: __device__ globals)
__device__ float g_Q[(size_t)Mr * Dm];
__device__ float g_K[(size_t)Mr * Dm];
__device__ float g_V[(size_t)Mr * Dm];
__device__ float g_AO[(size_t)Mr * Dm];
__device__ __nv_bfloat16 g_xhi[(size_t)Mr * Dm];
__device__ __nv_bfloat16 g_xlo[(size_t)Mr * Dm];
__device__ __nv_bfloat16 g_whi[4][(size_t)Dm * Dm];
__device__ __nv_bfloat16 g_wlo[4][(size_t)Dm * Dm];

// ===========================================================================
// PTX helpers (sm_80-class: valid on base compute_103 target)
// ===========================================================================
__device__ __forceinline__ uint32_t smem_to_u32(const void* p) {
    uint32_t a;
    asm("{ .reg .u64 t; cvta.to.shared.u64 t, %1; cvt.u32.u64 %0, t; }"
        : "=r"(a) : "l"(p));
    return a;
}

__device__ __forceinline__ void cp16(uint32_t dst, const void* src) {
    asm volatile("cp.async.cg.shared.global [%0], [%1], 16;" :: "r"(dst), "l"(src));
}
#define CP_COMMIT() asm volatile("cp.async.commit_group;" ::: "memory")
#define CP_WAIT1()  asm volatile("cp.async.wait_group 1;" ::: "memory")
#define CP_WAIT0()  asm volatile("cp.async.wait_group 0;" ::: "memory")

__device__ __forceinline__ void ldsm4(uint32_t* r, uint32_t addr) {
    asm volatile("ldmatrix.sync.aligned.m8n8.x4.shared.b16 {%0,%1,%2,%3}, [%4];"
        : "=r"(r[0]), "=r"(r[1]), "=r"(r[2]), "=r"(r[3]) : "r"(addr));
}

__device__ __forceinline__ void mma_bf16(float* d, const uint32_t* a,
                                         uint32_t b0, uint32_t b1) {
    asm volatile(
        "mma.sync.aligned.m16n8k16.row.col.f32.bf16.bf16.f32 "
        "{%0,%1,%2,%3}, {%4,%5,%6,%7}, {%8,%9}, {%0,%1,%2,%3};"
        : "+f"(d[0]), "+f"(d[1]), "+f"(d[2]), "+f"(d[3])
        : "r"(a[0]), "r"(a[1]), "r"(a[2]), "r"(a[3]), "r"(b0), "r"(b1));
}

// ===========================================================================
// fp32 -> bf16 hi/lo split (pure bandwidth)
// ===========================================================================
__global__ __launch_bounds__(256)
void cvt_hilo(const float* __restrict__ src, __nv_bfloat16* __restrict__ hi,
              __nv_bfloat16* __restrict__ lo, int n4)
{
    int i = blockIdx.x * blockDim.x + threadIdx.x;
    if (i >= n4) return;
    float4 v = reinterpret_cast<const float4*>(src)[i];
    __nv_bfloat16 h0 = __float2bfloat16(v.x);
    __nv_bfloat16 h1 = __float2bfloat16(v.y);
    __nv_bfloat16 h2 = __float2bfloat16(v.z);
    __nv_bfloat16 h3 = __float2bfloat16(v.w);
    __nv_bfloat16 l0 = __float2bfloat16(v.x - __bfloat162float(h0));
    __nv_bfloat16 l1 = __float2bfloat16(v.y - __bfloat162float(h1));
    __nv_bfloat16 l2 = __float2bfloat16(v.z - __bfloat162float(h2));
    __nv_bfloat16 l3 = __float2bfloat16(v.w - __bfloat162float(h3));
    reinterpret_cast<__nv_bfloat162*>(hi)[2 * i + 0] = __nv_bfloat162(h0, h1);
    reinterpret_cast<__nv_bfloat162*>(hi)[2 * i + 1] = __nv_bfloat162(h2, h3);
    reinterpret_cast<__nv_bfloat162*>(lo)[2 * i + 0] = __nv_bfloat162(l0, l1);
    reinterpret_cast<__nv_bfloat162*>(lo)[2 * i + 1] = __nv_bfloat162(l2, l3);
}

// ===========================================================================
// HMMA GEMM: C[M,N] = A[M,K] * B[N,K]^T + bias
// A,B given as bf16 hi/lo pairs. 3-pass compensated product.
// BM=BN=128, KC=32, 8 warps (32x64 warp tiles), cp.async double buffer.
// ===========================================================================
constexpr int TBM = 128, TBN = 128, TKC = 32;
constexpr int ROWB  = 80;           // 32 bf16 = 64B data + 16B pad
constexpr int TILEB = 128 * ROWB;   // 10240
constexpr int STAGEB = 4 * TILEB;   // 40960 (Ahi,Alo,Bhi,Blo)
constexpr int GSMEM = 2 * STAGEB;   // 81920

__device__ __forceinline__ void gemm_issue_chunk(
    const __nv_bfloat16* Ahi, const __nv_bfloat16* Alo,
    const __nv_bfloat16* Bhi, const __nv_bfloat16* Blo,
    uint32_t sb, int tid, int bm, int bn, int k0, int stage)
{
    #pragma unroll
    for (int i = 0; i < 8; i++) {
        int idx = tid + i * 256;       // 0..2047
        int tile = idx >> 9;           // 0 Ahi, 1 Alo, 2 Bhi, 3 Blo
        int row  = (idx >> 2) & 127;
        int c16  = idx & 3;
        const __nv_bfloat16* src;
        int grow;
        if (tile < 2) { grow = bm + row; src = (tile == 0) ? Ahi : Alo; }
        else          { grow = bn + row; src = (tile == 2) ? Bhi : Blo; }
        const char* gsrc = reinterpret_cast<const char*>(src + (size_t)grow * Dm + k0)
                           + c16 * 16;
        uint32_t dst = sb + stage * STAGEB + tile * TILEB + row * ROWB + c16 * 16;
        cp16(dst, gsrc);
    }
    CP_COMMIT();
}

__global__ __launch_bounds__(256, 2)
void gemm_mma(const __nv_bfloat16* __restrict__ Ahi, const __nv_bfloat16* __restrict__ Alo,
              const __nv_bfloat16* __restrict__ Bhi, const __nv_bfloat16* __restrict__ Blo,
              const float* __restrict__ bias, float* __restrict__ C, const int scatter)
{
    extern __shared__ char smem[];
    const uint32_t sb = smem_to_u32(smem);
    const int tid = threadIdx.x;
    const int wid = tid >> 5, lane = tid & 31;
    const int bm = blockIdx.y * TBM, bn = blockIdx.x * TBN;
    const int wr = wid & 3;       // m offset: wr*32
    const int wc = wid >> 2;      // n offset: wc*64

    float acc[2][8][4];
    #pragma unroll
    for (int a = 0; a < 2; a++)
        #pragma unroll
        for (int b = 0; b < 8; b++)
            #pragma unroll
            for (int c = 0; c < 4; c++) acc[a][b][c] = 0.f;

    // ldmatrix lane offsets
    const uint32_t aOff = (lane % 16) * ROWB + (lane / 16) * 16;
    const uint32_t bOff = (((lane >> 4) << 3) + (lane & 7)) * ROWB + ((lane >> 3) & 1) * 16;

    gemm_issue_chunk(Ahi, Alo, Bhi, Blo, sb, tid, bm, bn, 0, 0);

    const int NCK = Dm / TKC;    // 32
    for (int ck = 0; ck < NCK; ck++) {
        const int s = ck & 1;
        if (ck + 1 < NCK) {
            gemm_issue_chunk(Ahi, Alo, Bhi, Blo, sb, tid, bm, bn, (ck + 1) * TKC, s ^ 1);
            CP_WAIT1();
        } else {
            CP_WAIT0();
        }
        __syncthreads();

        const uint32_t stg = sb + s * STAGEB;
        const uint32_t aHiB = stg + 0 * TILEB + (wr * 32) * ROWB + aOff;
        const uint32_t aLoB = stg + 1 * TILEB + (wr * 32) * ROWB + aOff;
        const uint32_t bHiB = stg + 2 * TILEB + (wc * 64) * ROWB + bOff;
        const uint32_t bLoB = stg + 3 * TILEB + (wc * 64) * ROWB + bOff;

        #pragma unroll
        for (int ks = 0; ks < 2; ks++) {
            uint32_t ah[2][4], al[2][4];
            #pragma unroll
            for (int mt = 0; mt < 2; mt++) {
                ldsm4(ah[mt], aHiB + mt * 16 * ROWB + ks * 32);
                ldsm4(al[mt], aLoB + mt * 16 * ROWB + ks * 32);
            }
            #pragma unroll
            for (int nt = 0; nt < 4; nt++) {
                uint32_t bh[4], bl[4];
                ldsm4(bh, bHiB + nt * 16 * ROWB + ks * 32);
                ldsm4(bl, bLoB + nt * 16 * ROWB + ks * 32);
                #pragma unroll
                for (int mt = 0; mt < 2; mt++) {
                    mma_bf16(acc[mt][2 * nt + 0], ah[mt], bh[0], bh[1]);
                    mma_bf16(acc[mt][2 * nt + 1], ah[mt], bh[2], bh[3]);
                    mma_bf16(acc[mt][2 * nt + 0], ah[mt], bl[0], bl[1]);
                    mma_bf16(acc[mt][2 * nt + 1], ah[mt], bl[2], bl[3]);
                    mma_bf16(acc[mt][2 * nt + 0], al[mt], bh[0], bh[1]);
                    mma_bf16(acc[mt][2 * nt + 1], al[mt], bh[2], bh[3]);
                }
            }
        }
        __syncthreads();
    }

    // Epilogue
    const int grp = lane >> 2;         // 0..7
    const int qid = lane & 3;          // 0..3
    #pragma unroll
    for (int mt = 0; mt < 2; mt++) {
        #pragma unroll
        for (int na = 0; na < 8; na++) {
            const int n0 = bn + wc * 64 + na * 8 + qid * 2;
            const float b0 = bias[n0], b1 = bias[n0 + 1];
            #pragma unroll
            for (int half = 0; half < 2; half++) {
                const int m = bm + wr * 32 + mt * 16 + grp + half * 8;
                const float v0 = acc[mt][na][2 * half + 0] + b0;
                const float v1 = acc[mt][na][2 * half + 1] + b1;
                if (scatter == 0) {
                    *reinterpret_cast<float2*>(&C[(size_t)m * Dm + n0]) =
                        make_float2(v0, v1);
                } else {
                    const int b = m >> 11;
                    const int sI = m & 2047;
                    const int h = n0 >> 6;
                    const int d = n0 & 63;
                    *reinterpret_cast<float2*>(
                        &C[((((size_t)b * Hh + h) * Sq + sI) << 6) + d]) =
                        make_float2(v0, v1);
                }
            }
        }
    }
}

// ===========================================================================
// Flash attention (unchanged fp32 kernel — passed R1)
// ===========================================================================
constexpr int KVS = Dh + 1;
constexpr int SPS = FT + 1;
constexpr int FLASH_SMEM_FLOATS = FT * Dh + FT * KVS + FT * SPS + 3 * FT;
constexpr int FLASH_SMEM_BYTES = FLASH_SMEM_FLOATS * 4;

__global__ __launch_bounds__(256)
void flash_attn(const float* __restrict__ Q, const float* __restrict__ K,
                const float* __restrict__ V, float* __restrict__ AO)
{
    extern __shared__ float fsm[];
    float* Qs = fsm;
    float* KVs = Qs + FT * Dh;
    float* SP = KVs + FT * KVS;
    float* row_m = SP + FT * SPS;
    float* row_l = row_m + FT;
    float* row_r = row_l + FT;

    const int bh = blockIdx.y;
    const int qt = blockIdx.x;
    const int q0 = qt * FT;
    const int tid = threadIdx.x;
    const int ty = tid >> 4;
    const int tx = tid & 15;

    const float* Qb = Q + (size_t)bh * Sq * Dh;
    const float* Kb = K + (size_t)bh * Sq * Dh;
    const float* Vb = V + (size_t)bh * Sq * Dh;

    #pragma unroll
    for (int l = 0; l < 4; l++) {
        int f = tid + l * 256;
        int row = f >> 4;
        int c4 = (f & 15) << 2;
        float4 v = *reinterpret_cast<const float4*>(&Qb[(size_t)(q0 + row) * Dh + c4]);
        Qs[row * Dh + c4 + 0] = v.x; Qs[row * Dh + c4 + 1] = v.y;
        Qs[row * Dh + c4 + 2] = v.z; Qs[row * Dh + c4 + 3] = v.w;
    }
    if (tid < FT) { row_m[tid] = -1e30f; row_l[tid] = 0.f; }

    float o[4][4];
    #pragma unroll
    for (int r = 0; r < 4; r++)
        #pragma unroll
        for (int c = 0; c < 4; c++) o[r][c] = 0.f;

    __syncthreads();

    for (int kt = 0; kt <= qt; kt++) {
        const int k0 = kt * FT;
        #pragma unroll
        for (int l = 0; l < 4; l++) {
            int f = tid + l * 256;
            int row = f >> 4;
            int c4 = (f & 15) << 2;
            float4 v = *reinterpret_cast<const float4*>(&Kb[(size_t)(k0 + row) * Dh + c4]);
            KVs[row * KVS + c4 + 0] = v.x; KVs[row * KVS + c4 + 1] = v.y;
            KVs[row * KVS + c4 + 2] = v.z; KVs[row * KVS + c4 + 3] = v.w;
        }
        __syncthreads();

        float s[4][4];
        #pragma unroll
        for (int r = 0; r < 4; r++)
            #pragma unroll
            for (int c = 0; c < 4; c++) s[r][c] = 0.f;

        #pragma unroll 8
        for (int d = 0; d < Dh; d++) {
            float a[4], b[4];
            #pragma unroll
            for (int r = 0; r < 4; r++) a[r] = Qs[(ty * 4 + r) * Dh + d];
            #pragma unroll
            for (int c = 0; c < 4; c++) b[c] = KVs[(tx * 4 + c) * KVS + d];
            #pragma unroll
            for (int r = 0; r < 4; r++)
                #pragma unroll
                for (int c = 0; c < 4; c++)
                    s[r][c] = fmaf(a[r], b[c], s[r][c]);
        }

        const bool diag = (kt == qt);
        #pragma unroll
        for (int r = 0; r < 4; r++) {
            const int i = ty * 4 + r;
            #pragma unroll
            for (int c = 0; c < 4; c++) {
                const int j = tx * 4 + c;
                float v = s[r][c] * 0.125f;
                if (diag && j > i) v = -1e30f;
                SP[i * SPS + j] = v;
            }
        }
        __syncthreads();

        #pragma unroll
        for (int l = 0; l < 4; l++) {
            int f = tid + l * 256;
            int row = f >> 4;
            int c4 = (f & 15) << 2;
            float4 v = *reinterpret_cast<const float4*>(&Vb[(size_t)(k0 + row) * Dh + c4]);
            KVs[row * KVS + c4 + 0] = v.x; KVs[row * KVS + c4 + 1] = v.y;
            KVs[row * KVS + c4 + 2] = v.z; KVs[row * KVS + c4 + 3] = v.w;
        }

        if (tid < FT) {
            const int i = tid;
            const float m_old = row_m[i];
            float mx = m_old;
            #pragma unroll 8
            for (int j = 0; j < FT; j++) mx = fmaxf(mx, SP[i * SPS + j]);
            const float rf = __expf(m_old - mx);
            float sum = 0.f;
            #pragma unroll 8
            for (int j = 0; j < FT; j++) {
                const float p = __expf(SP[i * SPS + j] - mx);
                SP[i * SPS + j] = p;
                sum += p;
            }
            row_l[i] = row_l[i] * rf + sum;
            row_m[i] = mx;
            row_r[i] = rf;
        }
        __syncthreads();

        float rr[4];
        #pragma unroll
        for (int r = 0; r < 4; r++) rr[r] = row_r[ty * 4 + r];
        #pragma unroll
        for (int r = 0; r < 4; r++)
            #pragma unroll
            for (int c = 0; c < 4; c++) o[r][c] *= rr[r];

        #pragma unroll 8
        for (int j = 0; j < FT; j++) {
            float p[4], v[4];
            #pragma unroll
            for (int r = 0; r < 4; r++) p[r] = SP[(ty * 4 + r) * SPS + j];
            #pragma unroll
            for (int c = 0; c < 4; c++) v[c] = KVs[j * KVS + tx * 4 + c];
            #pragma unroll
            for (int r = 0; r < 4; r++)
                #pragma unroll
                for (int c = 0; c < 4; c++)
                    o[r][c] = fmaf(p[r], v[c], o[r][c]);
        }
        __syncthreads();
    }

    const int b = bh / Hh;
    const int h = bh % Hh;
    #pragma unroll
    for (int r = 0; r < 4; r++) {
        const int i = ty * 4 + r;
        const float inv = 1.0f / row_l[i];
        const int srow = q0 + i;
        #pragma unroll
        for (int c = 0; c < 4; c++) {
            const int d = tx * 4 + c;
            AO[((size_t)b * Sq + srow) * Dm + h * Dh + d] = o[r][c] * inv;
        }
    }
}

// ===========================================================================
extern "C" void kernel_launch(void* const* d_in, const int* in_sizes, int n_in,
                              void* d_out, int out_size)
{
    const float* x  = (const float*)d_in[0];
    const float* Wq = (const float*)d_in[2];
    const float* bq = (const float*)d_in[3];
    const float* Wk = (const float*)d_in[4];
    const float* bk = (const float*)d_in[5];
    const float* Wv = (const float*)d_in[6];
    const float* bv = (const float*)d_in[7];
    const float* Wo = (const float*)d_in[8];
    const float* bo = (const float*)d_in[9];
    float* out = (float*)d_out;

    float *gQ, *gK, *gV, *gAO;
    __nv_bfloat16 *xhi, *xlo, *whi, *wlo;
    cudaGetSymbolAddress((void**)&gQ, g_Q);
    cudaGetSymbolAddress((void**)&gK, g_K);
    cudaGetSymbolAddress((void**)&gV, g_V);
    cudaGetSymbolAddress((void**)&gAO, g_AO);
    cudaGetSymbolAddress((void**)&xhi, g_xhi);
    cudaGetSymbolAddress((void**)&xlo, g_xlo);
    cudaGetSymbolAddress((void**)&whi, g_whi);
    cudaGetSymbolAddress((void**)&wlo, g_wlo);

    static bool attr_set = false;
    if (!attr_set) {
        cudaFuncSetAttribute(flash_attn,
                             cudaFuncAttributeMaxDynamicSharedMemorySize,
                             FLASH_SMEM_BYTES);
        cudaFuncSetAttribute(gemm_mma,
                             cudaFuncAttributeMaxDynamicSharedMemorySize,
                             GSMEM);
        attr_set = true;
    }

    const size_t wN = (size_t)Dm * Dm;           // 1M elements per weight
    const int xn4 = Mr * Dm / 4;                 // 2M float4
    const int wn4 = (int)(wN / 4);               // 256K float4

    // Pre-convert x and weights to bf16 hi/lo
    cvt_hilo<<<(xn4 + 255) / 256, 256>>>(x, xhi, xlo, xn4);
    const float* Ws[4] = {Wq, Wk, Wv, Wo};
    for (int i = 0; i < 4; i++)
        cvt_hilo<<<(wn4 + 255) / 256, 256>>>(Ws[i], whi + i * wN, wlo + i * wN, wn4);

    const dim3 ggrid(Dm / TBN, Mr / TBM);        // (8, 64)
    gemm_mma<<<ggrid, 256, GSMEM>>>(xhi, xlo, whi + 0 * wN, wlo + 0 * wN, bq, gQ, 1);
    gemm_mma<<<ggrid, 256, GSMEM>>>(xhi, xlo, whi + 1 * wN, wlo + 1 * wN, bk, gK, 1);
    gemm_mma<<<ggrid, 256, GSMEM>>>(xhi, xlo, whi + 2 * wN, wlo + 2 * wN, bv, gV, 1);

    flash_attn<<<dim3(Sq / FT, Bz * Hh), 256, FLASH_SMEM_BYTES>>>(gQ, gK, gV, gAO);

    // Reuse xhi/xlo for the attention-output hi/lo split
    cvt_hilo<<<(xn4 + 255) / 256, 256>>>(gAO, xhi, xlo, xn4);
    gemm_mma<<<ggrid, 256, GSMEM>>>(xhi, xlo, whi + 3 * wN, wlo + 3 * wN, bo, out, 0);
}

// round 4
// speedup vs baseline: 3.3880x; 2.1232x over previous
#include <cuda_runtime.h>
#include <cuda_bf16.h>
#include <cuda_fp16.h>
#include <cstdint>
#include <math.h>

// Problem constants
constexpr int Bz = 4;
constexpr int Sq = 2048;
constexpr int Dm = 1024;
constexpr int Hh = 16;
constexpr int Dh = 64;
constexpr int Mr = Bz * Sq;    // 8192

// Scratch (allocation-free rule: __device__ globals)
__device__ __nv_bfloat16 g_xhi[(size_t)Mr * Dm];
__device__ __nv_bfloat16 g_xlo[(size_t)Mr * Dm];
__device__ __nv_bfloat16 g_whi[4][(size_t)Dm * Dm];
__device__ __nv_bfloat16 g_wlo[4][(size_t)Dm * Dm];
__device__ __nv_bfloat16 g_Qhi[(size_t)Mr * Dm];
__device__ __nv_bfloat16 g_Qlo[(size_t)Mr * Dm];
__device__ __nv_bfloat16 g_Khi[(size_t)Mr * Dm];
__device__ __nv_bfloat16 g_Klo[(size_t)Mr * Dm];
__device__ __half        g_Vh [(size_t)Mr * Dm];

// ===========================================================================
// PTX helpers
// ===========================================================================
__device__ __forceinline__ uint32_t smem_to_u32(const void* p) {
    uint32_t a;
    asm("{ .reg .u64 t; cvta.to.shared.u64 t, %1; cvt.u32.u64 %0, t; }"
        : "=r"(a) : "l"(p));
    return a;
}
__device__ __forceinline__ void cp16(uint32_t dst, const void* src) {
    asm volatile("cp.async.cg.shared.global [%0], [%1], 16;" :: "r"(dst), "l"(src));
}
#define CP_COMMIT() asm volatile("cp.async.commit_group;" ::: "memory")
#define CP_WAIT1()  asm volatile("cp.async.wait_group 1;" ::: "memory")
#define CP_WAIT0()  asm volatile("cp.async.wait_group 0;" ::: "memory")

__device__ __forceinline__ void ldsm4(uint32_t* r, uint32_t addr) {
    asm volatile("ldmatrix.sync.aligned.m8n8.x4.shared.b16 {%0,%1,%2,%3}, [%4];"
        : "=r"(r[0]), "=r"(r[1]), "=r"(r[2]), "=r"(r[3]) : "r"(addr));
}
__device__ __forceinline__ void ldsm4t(uint32_t* r, uint32_t addr) {
    asm volatile("ldmatrix.sync.aligned.m8n8.x4.trans.shared.b16 {%0,%1,%2,%3}, [%4];"
        : "=r"(r[0]), "=r"(r[1]), "=r"(r[2]), "=r"(r[3]) : "r"(addr));
}
__device__ __forceinline__ void mma_bf16(float* d, const uint32_t* a,
                                         uint32_t b0, uint32_t b1) {
    asm volatile(
        "mma.sync.aligned.m16n8k16.row.col.f32.bf16.bf16.f32 "
        "{%0,%1,%2,%3}, {%4,%5,%6,%7}, {%8,%9}, {%0,%1,%2,%3};"
        : "+f"(d[0]), "+f"(d[1]), "+f"(d[2]), "+f"(d[3])
        : "r"(a[0]), "r"(a[1]), "r"(a[2]), "r"(a[3]), "r"(b0), "r"(b1));
}
__device__ __forceinline__ void mma_f16(float* d, const uint32_t* a,
                                        uint32_t b0, uint32_t b1) {
    asm volatile(
        "mma.sync.aligned.m16n8k16.row.col.f32.f16.f16.f32 "
        "{%0,%1,%2,%3}, {%4,%5,%6,%7}, {%8,%9}, {%0,%1,%2,%3};"
        : "+f"(d[0]), "+f"(d[1]), "+f"(d[2]), "+f"(d[3])
        : "r"(a[0]), "r"(a[1]), "r"(a[2]), "r"(a[3]), "r"(b0), "r"(b1));
}

// ===========================================================================
// fp32 -> bf16 hi/lo split (pure bandwidth)
// ===========================================================================
__global__ __launch_bounds__(256)
void cvt_hilo(const float* __restrict__ src, __nv_bfloat16* __restrict__ hi,
              __nv_bfloat16* __restrict__ lo, int n4)
{
    int i = blockIdx.x * blockDim.x + threadIdx.x;
    if (i >= n4) return;
    float4 v = reinterpret_cast<const float4*>(src)[i];
    __nv_bfloat16 h0 = __float2bfloat16(v.x);
    __nv_bfloat16 h1 = __float2bfloat16(v.y);
    __nv_bfloat16 h2 = __float2bfloat16(v.z);
    __nv_bfloat16 h3 = __float2bfloat16(v.w);
    __nv_bfloat16 l0 = __float2bfloat16(v.x - __bfloat162float(h0));
    __nv_bfloat16 l1 = __float2bfloat16(v.y - __bfloat162float(h1));
    __nv_bfloat16 l2 = __float2bfloat16(v.z - __bfloat162float(h2));
    __nv_bfloat16 l3 = __float2bfloat16(v.w - __bfloat162float(h3));
    reinterpret_cast<__nv_bfloat162*>(hi)[2 * i + 0] = __nv_bfloat162(h0, h1);
    reinterpret_cast<__nv_bfloat162*>(hi)[2 * i + 1] = __nv_bfloat162(h2, h3);
    reinterpret_cast<__nv_bfloat162*>(lo)[2 * i + 0] = __nv_bfloat162(l0, l1);
    reinterpret_cast<__nv_bfloat162*>(lo)[2 * i + 1] = __nv_bfloat162(l2, l3);
}

// ===========================================================================
// HMMA GEMM: C[M,N] = A[M,K] * B[N,K]^T + bias (A,B bf16 hi/lo, 3-pass)
// mode 0: fp32 row-major -> C
// mode 1: bf16 hi/lo scatter [b,h,s,d] -> Chi, Clo
// mode 2: fp16 scatter [b,h,s,d] -> Cv
// ===========================================================================
constexpr int TBM = 128, TBN = 128, TKC = 32;
constexpr int ROWB  = 80;
constexpr int TILEB = 128 * ROWB;
constexpr int STAGEB = 4 * TILEB;
constexpr int GSMEM = 2 * STAGEB;   // 81920

__device__ __forceinline__ void gemm_issue_chunk(
    const __nv_bfloat16* Ahi, const __nv_bfloat16* Alo,
    const __nv_bfloat16* Bhi, const __nv_bfloat16* Blo,
    uint32_t sb, int tid, int bm, int bn, int k0, int stage)
{
    #pragma unroll
    for (int i = 0; i < 8; i++) {
        int idx = tid + i * 256;
        int tile = idx >> 9;
        int row  = (idx >> 2) & 127;
        int c16  = idx & 3;
        const __nv_bfloat16* src;
        int grow;
        if (tile < 2) { grow = bm + row; src = (tile == 0) ? Ahi : Alo; }
        else          { grow = bn + row; src = (tile == 2) ? Bhi : Blo; }
        const char* gsrc = reinterpret_cast<const char*>(src + (size_t)grow * Dm + k0)
                           + c16 * 16;
        uint32_t dst = sb + stage * STAGEB + tile * TILEB + row * ROWB + c16 * 16;
        cp16(dst, gsrc);
    }
    CP_COMMIT();
}

__global__ __launch_bounds__(256, 2)
void gemm_mma(const __nv_bfloat16* __restrict__ Ahi, const __nv_bfloat16* __restrict__ Alo,
              const __nv_bfloat16* __restrict__ Bhi, const __nv_bfloat16* __restrict__ Blo,
              const float* __restrict__ bias, float* __restrict__ C,
              __nv_bfloat16* __restrict__ Chi, __nv_bfloat16* __restrict__ Clo,
              __half* __restrict__ Cv, const int mode)
{
    extern __shared__ char smem[];
    const uint32_t sb = smem_to_u32(smem);
    const int tid = threadIdx.x;
    const int wid = tid >> 5, lane = tid & 31;
    const int bm = blockIdx.y * TBM, bn = blockIdx.x * TBN;
    const int wr = wid & 3;
    const int wc = wid >> 2;

    float acc[2][8][4];
    #pragma unroll
    for (int a = 0; a < 2; a++)
        #pragma unroll
        for (int b = 0; b < 8; b++)
            #pragma unroll
            for (int c = 0; c < 4; c++) acc[a][b][c] = 0.f;

    const uint32_t aOff = (lane % 16) * ROWB + (lane / 16) * 16;
    const uint32_t bOff = (((lane >> 4) << 3) + (lane & 7)) * ROWB + ((lane >> 3) & 1) * 16;

    gemm_issue_chunk(Ahi, Alo, Bhi, Blo, sb, tid, bm, bn, 0, 0);

    const int NCK = Dm / TKC;
    for (int ck = 0; ck < NCK; ck++) {
        const int s = ck & 1;
        if (ck + 1 < NCK) {
            gemm_issue_chunk(Ahi, Alo, Bhi, Blo, sb, tid, bm, bn, (ck + 1) * TKC, s ^ 1);
            CP_WAIT1();
        } else {
            CP_WAIT0();
        }
        __syncthreads();

        const uint32_t stg = sb + s * STAGEB;
        const uint32_t aHiB = stg + 0 * TILEB + (wr * 32) * ROWB + aOff;
        const uint32_t aLoB = stg + 1 * TILEB + (wr * 32) * ROWB + aOff;
        const uint32_t bHiB = stg + 2 * TILEB + (wc * 64) * ROWB + bOff;
        const uint32_t bLoB = stg + 3 * TILEB + (wc * 64) * ROWB + bOff;

        #pragma unroll
        for (int ks = 0; ks < 2; ks++) {
            uint32_t ah[2][4], al[2][4];
            #pragma unroll
            for (int mt = 0; mt < 2; mt++) {
                ldsm4(ah[mt], aHiB + mt * 16 * ROWB + ks * 32);
                ldsm4(al[mt], aLoB + mt * 16 * ROWB + ks * 32);
            }
            #pragma unroll
            for (int nt = 0; nt < 4; nt++) {
                uint32_t bh[4], bl[4];
                ldsm4(bh, bHiB + nt * 16 * ROWB + ks * 32);
                ldsm4(bl, bLoB + nt * 16 * ROWB + ks * 32);
                #pragma unroll
                for (int mt = 0; mt < 2; mt++) {
                    mma_bf16(acc[mt][2 * nt + 0], ah[mt], bh[0], bh[1]);
                    mma_bf16(acc[mt][2 * nt + 1], ah[mt], bh[2], bh[3]);
                    mma_bf16(acc[mt][2 * nt + 0], ah[mt], bl[0], bl[1]);
                    mma_bf16(acc[mt][2 * nt + 1], ah[mt], bl[2], bl[3]);
                    mma_bf16(acc[mt][2 * nt + 0], al[mt], bh[0], bh[1]);
                    mma_bf16(acc[mt][2 * nt + 1], al[mt], bh[2], bh[3]);
                }
            }
        }
        __syncthreads();
    }

    const int grp = lane >> 2;
    const int qid = lane & 3;
    #pragma unroll
    for (int mt = 0; mt < 2; mt++) {
        #pragma unroll
        for (int na = 0; na < 8; na++) {
            const int n0 = bn + wc * 64 + na * 8 + qid * 2;
            const float b0 = bias[n0], b1 = bias[n0 + 1];
            #pragma unroll
            for (int half = 0; half < 2; half++) {
                const int m = bm + wr * 32 + mt * 16 + grp + half * 8;
                const float v0 = acc[mt][na][2 * half + 0] + b0;
                const float v1 = acc[mt][na][2 * half + 1] + b1;
                if (mode == 0) {
                    *reinterpret_cast<float2*>(&C[(size_t)m * Dm + n0]) =
                        make_float2(v0, v1);
                } else {
                    const int b = m >> 11;
                    const int sI = m & 2047;
                    const int h = n0 >> 6;
                    const int d = n0 & 63;
                    const size_t o = ((((size_t)b * Hh + h) * Sq + sI) << 6) + d;
                    if (mode == 1) {
                        __nv_bfloat16 h0 = __float2bfloat16(v0);
                        __nv_bfloat16 h1 = __float2bfloat16(v1);
                        __nv_bfloat16 l0 = __float2bfloat16(v0 - __bfloat162float(h0));
                        __nv_bfloat16 l1 = __float2bfloat16(v1 - __bfloat162float(h1));
                        *reinterpret_cast<__nv_bfloat162*>(&Chi[o]) = __nv_bfloat162(h0, h1);
                        *reinterpret_cast<__nv_bfloat162*>(&Clo[o]) = __nv_bfloat162(l0, l1);
                    } else {
                        *reinterpret_cast<__half2*>(&Cv[o]) =
                            __floats2half2_rn(v0, v1);
                    }
                }
            }
        }
    }
}

// ===========================================================================
// Tensor-core flash attention.
// Block: 128 q-rows, 8 warps (m16 each). K/V tiles 64 wide.
// QK^T: bf16 hi/lo 3-pass. P*V: fp16 1-pass, P stays in registers.
// Output written as bf16 hi/lo row-major [b*s, Dm] directly into xhi/xlo.
// ===========================================================================
constexpr int FBQ = 128, FBK = 64;
constexpr int FROWB = 144;                   // 64 elems*2B + 16B pad
constexpr int F_QH = 0;
constexpr int F_QL = F_QH + FBQ * FROWB;     // 18432
constexpr int F_KH = F_QL + FBQ * FROWB;     // 36864
constexpr int F_KL = F_KH + FBK * FROWB;     // 46080
constexpr int F_V  = F_KL + FBK * FROWB;     // 55296
constexpr int FSMEM = F_V + FBK * FROWB;     // 64512

__global__ __launch_bounds__(256, 2)
void flash_tc(const __nv_bfloat16* __restrict__ Qhi, const __nv_bfloat16* __restrict__ Qlo,
              const __nv_bfloat16* __restrict__ Khi, const __nv_bfloat16* __restrict__ Klo,
              const __half* __restrict__ Vh,
              __nv_bfloat16* __restrict__ Ohi, __nv_bfloat16* __restrict__ Olo)
{
    extern __shared__ char smem[];
    const uint32_t sb = smem_to_u32(smem);
    const int tid = threadIdx.x;
    const int w = tid >> 5, lane = tid & 31;
    const int grp = lane >> 2, qid = lane & 3;

    const int bh = blockIdx.y;
    const int qt = gridDim.x - 1 - blockIdx.x;   // big tiles first
    const int q0 = qt * FBQ;
    const size_t rowbase = (size_t)bh * Sq;      // Q/K/V row offset for this head

    constexpr float SCALE = 0.18033688011112042f;  // (1/8) * log2(e)

    // --- load Q tile (hi+lo): 2048 16B chunks, 8 per thread ---
    #pragma unroll
    for (int i = 0; i < 8; i++) {
        int idx = tid + i * 256;
        int arr = idx >> 10;
        int row = (idx >> 3) & 127;
        int c = idx & 7;
        const __nv_bfloat16* src = arr ? Qlo : Qhi;
        cp16(sb + (arr ? F_QL : F_QH) + row * FROWB + c * 16,
             reinterpret_cast<const char*>(src + (rowbase + q0 + row) * Dh) + c * 16);
    }
    CP_COMMIT();

    // per-warp state (rows grp and grp+8 of this warp's m16)
    float m0 = -1e30f, m1 = -1e30f, l0 = 0.f, l1 = 0.f;
    float o[8][4];
    #pragma unroll
    for (int t = 0; t < 8; t++)
        #pragma unroll
        for (int i = 0; i < 4; i++) o[t][i] = 0.f;

    const int rw0 = q0 + w * 16;      // warp's min global q row
    const uint32_t aOffQ = sb + F_QH + (w * 16 + lane % 16) * FROWB + (lane / 16) * 16;
    const uint32_t bOffK = (((lane >> 4) << 3) + (lane & 7)) * FROWB + ((lane >> 3) & 1) * 16;

    const int KT = 2 * (qt + 1);
    for (int kt = 0; kt < KT; kt++) {
        const int k0 = kt * FBK;
        // --- load K(hi,lo) + V tiles: 1536 chunks, 6 per thread ---
        #pragma unroll
        for (int i = 0; i < 6; i++) {
            int idx = tid + i * 256;
            int arr = idx >> 9;               // 0=Khi 1=Klo 2=V
            int row = (idx >> 3) & 63;
            int c = idx & 7;
            const char* src;
            uint32_t base;
            if (arr == 0) { src = (const char*)(Khi + (rowbase + k0 + row) * Dh); base = F_KH; }
            else if (arr == 1) { src = (const char*)(Klo + (rowbase + k0 + row) * Dh); base = F_KL; }
            else { src = (const char*)(Vh + (rowbase + k0 + row) * Dh); base = F_V; }
            cp16(sb + base + row * FROWB + c * 16, src + c * 16);
        }
        CP_COMMIT();
        CP_WAIT0();
        __syncthreads();

        if (k0 <= rw0 + 15) {   // warp has unmasked work in this tile
            // ---- S = Q K^T (bf16 hi/lo, 3-pass) ----
            float sc[8][4];
            #pragma unroll
            for (int t = 0; t < 8; t++)
                #pragma unroll
                for (int i = 0; i < 4; i++) sc[t][i] = 0.f;

            #pragma unroll
            for (int ks = 0; ks < 4; ks++) {
                uint32_t ah[4], al[4];
                ldsm4(ah, aOffQ + ks * 32);
                ldsm4(al, aOffQ + (F_QL - F_QH) + ks * 32);
                #pragma unroll
                for (int ntp = 0; ntp < 4; ntp++) {
                    uint32_t bh[4], bl[4];
                    uint32_t kaddr = sb + F_KH + ntp * 16 * FROWB + bOffK + ks * 32;
                    ldsm4(bh, kaddr);
                    ldsm4(bl, kaddr + (F_KL - F_KH));
                    mma_bf16(sc[2 * ntp + 0], ah, bh[0], bh[1]);
                    mma_bf16(sc[2 * ntp + 1], ah, bh[2], bh[3]);
                    mma_bf16(sc[2 * ntp + 0], ah, bl[0], bl[1]);
                    mma_bf16(sc[2 * ntp + 1], ah, bl[2], bl[3]);
                    mma_bf16(sc[2 * ntp + 0], al, bh[0], bh[1]);
                    mma_bf16(sc[2 * ntp + 1], al, bh[2], bh[3]);
                }
            }

            // ---- scale + causal mask ----
            const bool needMask = (k0 + FBK - 1 > rw0);
            const int r0g = rw0 + grp, r1g = r0g + 8;
            #pragma unroll
            for (int t = 0; t < 8; t++) {
                #pragma unroll
                for (int i = 0; i < 4; i++) sc[t][i] *= SCALE;
                if (needMask) {
                    const int jc = k0 + t * 8 + qid * 2;
                    if (jc + 0 > r0g) sc[t][0] = -1e4f;
                    if (jc + 1 > r0g) sc[t][1] = -1e4f;
                    if (jc + 0 > r1g) sc[t][2] = -1e4f;
                    if (jc + 1 > r1g) sc[t][3] = -1e4f;
                }
            }

            // ---- online softmax (register, exp2 domain) ----
            float mx0 = sc[0][0], mx1 = sc[0][2];
            #pragma unroll
            for (int t = 0; t < 8; t++) {
                mx0 = fmaxf(mx0, fmaxf(sc[t][0], sc[t][1]));
                mx1 = fmaxf(mx1, fmaxf(sc[t][2], sc[t][3]));
            }
            mx0 = fmaxf(mx0, __shfl_xor_sync(0xffffffff, mx0, 1));
            mx0 = fmaxf(mx0, __shfl_xor_sync(0xffffffff, mx0, 2));
            mx1 = fmaxf(mx1, __shfl_xor_sync(0xffffffff, mx1, 1));
            mx1 = fmaxf(mx1, __shfl_xor_sync(0xffffffff, mx1, 2));
            const float nm0 = fmaxf(m0, mx0), nm1 = fmaxf(m1, mx1);
            const float f0 = exp2f(m0 - nm0), f1 = exp2f(m1 - nm1);
            m0 = nm0; m1 = nm1;

            uint32_t pp[8][2];
            float sum0 = 0.f, sum1 = 0.f;
            #pragma unroll
            for (int t = 0; t < 8; t++) {
                const float p0 = exp2f(sc[t][0] - m0);
                const float p1 = exp2f(sc[t][1] - m0);
                const float p2 = exp2f(sc[t][2] - m1);
                const float p3 = exp2f(sc[t][3] - m1);
                sum0 += p0 + p1; sum1 += p2 + p3;
                __half2 h01 = __floats2half2_rn(p0, p1);
                __half2 h23 = __floats2half2_rn(p2, p3);
                pp[t][0] = *reinterpret_cast<uint32_t*>(&h01);
                pp[t][1] = *reinterpret_cast<uint32_t*>(&h23);
            }
            sum0 += __shfl_xor_sync(0xffffffff, sum0, 1);
            sum0 += __shfl_xor_sync(0xffffffff, sum0, 2);
            sum1 += __shfl_xor_sync(0xffffffff, sum1, 1);
            sum1 += __shfl_xor_sync(0xffffffff, sum1, 2);
            l0 = l0 * f0 + sum0;
            l1 = l1 * f1 + sum1;

            // rescale O
            #pragma unroll
            for (int t = 0; t < 8; t++) {
                o[t][0] *= f0; o[t][1] *= f0; o[t][2] *= f1; o[t][3] *= f1;
            }

            // ---- O += P * V (fp16 1-pass, P in regs, V via ldmatrix.trans) ----
            #pragma unroll
            for (int kk = 0; kk < 4; kk++) {
                uint32_t a[4] = { pp[2 * kk][0], pp[2 * kk][1],
                                  pp[2 * kk + 1][0], pp[2 * kk + 1][1] };
                #pragma unroll
                for (int ntp = 0; ntp < 4; ntp++) {
                    uint32_t bv[4];
                    ldsm4t(bv, sb + F_V + (kk * 16 + (lane & 15)) * FROWB
                               + (2 * ntp + (lane >> 4)) * 16);
                    mma_f16(o[2 * ntp + 0], a, bv[0], bv[1]);
                    mma_f16(o[2 * ntp + 1], a, bv[2], bv[3]);
                }
            }
        }
        __syncthreads();   // all warps done with K/V before next overwrite
    }

    // ---- epilogue: write bf16 hi/lo row-major [b*s, Dm] ----
    const int b = bh >> 4, h = bh & 15;
    const float inv0 = 1.0f / l0, inv1 = 1.0f / l1;
    const size_t row0 = ((size_t)b * Sq + (q0 + w * 16 + grp)) * Dm + h * Dh;
    const size_t row1 = row0 + 8 * Dm;
    #pragma unroll
    for (int t = 0; t < 8; t++) {
        const int col = t * 8 + qid * 2;
        const float v0 = o[t][0] * inv0, v1 = o[t][1] * inv0;
        const float v2 = o[t][2] * inv1, v3 = o[t][3] * inv1;
        __nv_bfloat16 h0 = __float2bfloat16(v0), h1 = __float2bfloat16(v1);
        __nv_bfloat16 h2 = __float2bfloat16(v2), h3 = __float2bfloat16(v3);
        *reinterpret_cast<__nv_bfloat162*>(&Ohi[row0 + col]) = __nv_bfloat162(h0, h1);
        *reinterpret_cast<__nv_bfloat162*>(&Ohi[row1 + col]) = __nv_bfloat162(h2, h3);
        __nv_bfloat16 e0 = __float2bfloat16(v0 - __bfloat162float(h0));
        __nv_bfloat16 e1 = __float2bfloat16(v1 - __bfloat162float(h1));
        __nv_bfloat16 e2 = __float2bfloat16(v2 - __bfloat162float(h2));
        __nv_bfloat16 e3 = __float2bfloat16(v3 - __bfloat162float(h3));
        *reinterpret_cast<__nv_bfloat162*>(&Olo[row0 + col]) = __nv_bfloat162(e0, e1);
        *reinterpret_cast<__nv_bfloat162*>(&Olo[row1 + col]) = __nv_bfloat162(e2, e3);
    }
}

// ===========================================================================
extern "C" void kernel_launch(void* const* d_in, const int* in_sizes, int n_in,
                              void* d_out, int out_size)
{
    const float* x  = (const float*)d_in[0];
    const float* Wq = (const float*)d_in[2];
    const float* bq = (const float*)d_in[3];
    const float* Wk = (const float*)d_in[4];
    const float* bk = (const float*)d_in[5];
    const float* Wv = (const float*)d_in[6];
    const float* bv = (const float*)d_in[7];
    const float* Wo = (const float*)d_in[8];
    const float* bo = (const float*)d_in[9];
    float* out = (float*)d_out;

    __nv_bfloat16 *xhi, *xlo, *whi, *wlo, *qhi, *qlo, *khi, *klo;
    __half* vh;
    cudaGetSymbolAddress((void**)&xhi, g_xhi);
    cudaGetSymbolAddress((void**)&xlo, g_xlo);
    cudaGetSymbolAddress((void**)&whi, g_whi);
    cudaGetSymbolAddress((void**)&wlo, g_wlo);
    cudaGetSymbolAddress((void**)&qhi, g_Qhi);
    cudaGetSymbolAddress((void**)&qlo, g_Qlo);
    cudaGetSymbolAddress((void**)&khi, g_Khi);
    cudaGetSymbolAddress((void**)&klo, g_Klo);
    cudaGetSymbolAddress((void**)&vh, g_Vh);

    static bool attr_set = false;
    if (!attr_set) {
        cudaFuncSetAttribute(gemm_mma, cudaFuncAttributeMaxDynamicSharedMemorySize, GSMEM);
        cudaFuncSetAttribute(flash_tc, cudaFuncAttributeMaxDynamicSharedMemorySize, FSMEM);
        attr_set = true;
    }

    const size_t wN = (size_t)Dm * Dm;
    const int xn4 = Mr * Dm / 4;
    const int wn4 = (int)(wN / 4);

    cvt_hilo<<<(xn4 + 255) / 256, 256>>>(x, xhi, xlo, xn4);
    const float* Ws[4] = {Wq, Wk, Wv, Wo};
    for (int i = 0; i < 4; i++)
        cvt_hilo<<<(wn4 + 255) / 256, 256>>>(Ws[i], whi + i * wN, wlo + i * wN, wn4);

    const dim3 ggrid(Dm / TBN, Mr / TBM);   // (8, 64)
    gemm_mma<<<ggrid, 256, GSMEM>>>(xhi, xlo, whi + 0 * wN, wlo + 0 * wN, bq,
                                    nullptr, qhi, qlo, nullptr, 1);
    gemm_mma<<<ggrid, 256, GSMEM>>>(xhi, xlo, whi + 1 * wN, wlo + 1 * wN, bk,
                                    nullptr, khi, klo, nullptr, 1);
    gemm_mma<<<ggrid, 256, GSMEM>>>(xhi, xlo, whi + 2 * wN, wlo + 2 * wN, bv,
                                    nullptr, nullptr, nullptr, vh, 2);

    // flash writes its bf16 hi/lo output over xhi/xlo (x no longer needed)
    flash_tc<<<dim3(Sq / FBQ, Bz * Hh), 256, FSMEM>>>(qhi, qlo, khi, klo, vh, xhi, xlo);

    gemm_mma<<<ggrid, 256, GSMEM>>>(xhi, xlo, whi + 3 * wN, wlo + 3 * wN, bo,
                                    out, nullptr, nullptr, nullptr, 0);
}

// round 5
// speedup vs baseline: 4.2886x; 1.2658x over previous
#include <cuda_runtime.h>
#include <cuda_bf16.h>
#include <cuda_fp16.h>
#include <cstdint>
#include <math.h>

// Problem constants
constexpr int Bz = 4;
constexpr int Sq = 2048;
constexpr int Dm = 1024;
constexpr int Hh = 16;
constexpr int Dh = 64;
constexpr int Mr = Bz * Sq;    // 8192

// Scratch (allocation-free rule: __device__ globals)
__device__ __nv_bfloat16 g_xhi[(size_t)Mr * Dm];
__device__ __nv_bfloat16 g_xlo[(size_t)Mr * Dm];
__device__ __half        g_xh [(size_t)Mr * Dm];     // x fp16, then reused for O fp16
__device__ __nv_bfloat16 g_whi[2][(size_t)Dm * Dm];  // Wq, Wk
__device__ __nv_bfloat16 g_wlo[2][(size_t)Dm * Dm];
__device__ __half        g_wh16[2][(size_t)Dm * Dm]; // Wv, Wo
__device__ __nv_bfloat16 g_Qhi[(size_t)Mr * Dm];
__device__ __nv_bfloat16 g_Qlo[(size_t)Mr * Dm];
__device__ __nv_bfloat16 g_Khi[(size_t)Mr * Dm];
__device__ __nv_bfloat16 g_Klo[(size_t)Mr * Dm];
__device__ __half        g_Vh [(size_t)Mr * Dm];

// ===========================================================================
// PTX helpers
// ===========================================================================
__device__ __forceinline__ uint32_t smem_to_u32(const void* p) {
    uint32_t a;
    asm("{ .reg .u64 t; cvta.to.shared.u64 t, %1; cvt.u32.u64 %0, t; }"
        : "=r"(a) : "l"(p));
    return a;
}
__device__ __forceinline__ void cp16(uint32_t dst, const void* src) {
    asm volatile("cp.async.cg.shared.global [%0], [%1], 16;" :: "r"(dst), "l"(src));
}
#define CP_COMMIT() asm volatile("cp.async.commit_group;" ::: "memory")
#define CP_WAIT1()  asm volatile("cp.async.wait_group 1;" ::: "memory")
#define CP_WAIT0()  asm volatile("cp.async.wait_group 0;" ::: "memory")

__device__ __forceinline__ void ldsm4(uint32_t* r, uint32_t addr) {
    asm volatile("ldmatrix.sync.aligned.m8n8.x4.shared.b16 {%0,%1,%2,%3}, [%4];"
        : "=r"(r[0]), "=r"(r[1]), "=r"(r[2]), "=r"(r[3]) : "r"(addr));
}
__device__ __forceinline__ void ldsm4t(uint32_t* r, uint32_t addr) {
    asm volatile("ldmatrix.sync.aligned.m8n8.x4.trans.shared.b16 {%0,%1,%2,%3}, [%4];"
        : "=r"(r[0]), "=r"(r[1]), "=r"(r[2]), "=r"(r[3]) : "r"(addr));
}
__device__ __forceinline__ void mma_bf16(float* d, const uint32_t* a,
                                         uint32_t b0, uint32_t b1) {
    asm volatile(
        "mma.sync.aligned.m16n8k16.row.col.f32.bf16.bf16.f32 "
        "{%0,%1,%2,%3}, {%4,%5,%6,%7}, {%8,%9}, {%0,%1,%2,%3};"
        : "+f"(d[0]), "+f"(d[1]), "+f"(d[2]), "+f"(d[3])
        : "r"(a[0]), "r"(a[1]), "r"(a[2]), "r"(a[3]), "r"(b0), "r"(b1));
}
__device__ __forceinline__ void mma_f16(float* d, const uint32_t* a,
                                        uint32_t b0, uint32_t b1) {
    asm volatile(
        "mma.sync.aligned.m16n8k16.row.col.f32.f16.f16.f32 "
        "{%0,%1,%2,%3}, {%4,%5,%6,%7}, {%8,%9}, {%0,%1,%2,%3};"
        : "+f"(d[0]), "+f"(d[1]), "+f"(d[2]), "+f"(d[3])
        : "r"(a[0]), "r"(a[1]), "r"(a[2]), "r"(a[3]), "r"(b0), "r"(b1));
}

// ===========================================================================
// Conversion kernels (pure bandwidth)
// ===========================================================================
__global__ __launch_bounds__(256)
void cvt_hilo(const float* __restrict__ src, __nv_bfloat16* __restrict__ hi,
              __nv_bfloat16* __restrict__ lo, int n4)
{
    int i = blockIdx.x * blockDim.x + threadIdx.x;
    if (i >= n4) return;
    float4 v = reinterpret_cast<const float4*>(src)[i];
    __nv_bfloat16 h0 = __float2bfloat16(v.x);
    __nv_bfloat16 h1 = __float2bfloat16(v.y);
    __nv_bfloat16 h2 = __float2bfloat16(v.z);
    __nv_bfloat16 h3 = __float2bfloat16(v.w);
    __nv_bfloat16 l0 = __float2bfloat16(v.x - __bfloat162float(h0));
    __nv_bfloat16 l1 = __float2bfloat16(v.y - __bfloat162float(h1));
    __nv_bfloat16 l2 = __float2bfloat16(v.z - __bfloat162float(h2));
    __nv_bfloat16 l3 = __float2bfloat16(v.w - __bfloat162float(h3));
    reinterpret_cast<__nv_bfloat162*>(hi)[2 * i + 0] = __nv_bfloat162(h0, h1);
    reinterpret_cast<__nv_bfloat162*>(hi)[2 * i + 1] = __nv_bfloat162(h2, h3);
    reinterpret_cast<__nv_bfloat162*>(lo)[2 * i + 0] = __nv_bfloat162(l0, l1);
    reinterpret_cast<__nv_bfloat162*>(lo)[2 * i + 1] = __nv_bfloat162(l2, l3);
}

__global__ __launch_bounds__(256)
void cvt_f16(const float* __restrict__ src, __half* __restrict__ dst, int n4)
{
    int i = blockIdx.x * blockDim.x + threadIdx.x;
    if (i >= n4) return;
    float4 v = reinterpret_cast<const float4*>(src)[i];
    reinterpret_cast<__half2*>(dst)[2 * i + 0] = __floats2half2_rn(v.x, v.y);
    reinterpret_cast<__half2*>(dst)[2 * i + 1] = __floats2half2_rn(v.z, v.w);
}

// x -> bf16 hi/lo + fp16, single pass
__global__ __launch_bounds__(256)
void cvt_all(const float* __restrict__ src, __nv_bfloat16* __restrict__ hi,
             __nv_bfloat16* __restrict__ lo, __half* __restrict__ f16, int n4)
{
    int i = blockIdx.x * blockDim.x + threadIdx.x;
    if (i >= n4) return;
    float4 v = reinterpret_cast<const float4*>(src)[i];
    __nv_bfloat16 h0 = __float2bfloat16(v.x);
    __nv_bfloat16 h1 = __float2bfloat16(v.y);
    __nv_bfloat16 h2 = __float2bfloat16(v.z);
    __nv_bfloat16 h3 = __float2bfloat16(v.w);
    __nv_bfloat16 l0 = __float2bfloat16(v.x - __bfloat162float(h0));
    __nv_bfloat16 l1 = __float2bfloat16(v.y - __bfloat162float(h1));
    __nv_bfloat16 l2 = __float2bfloat16(v.z - __bfloat162float(h2));
    __nv_bfloat16 l3 = __float2bfloat16(v.w - __bfloat162float(h3));
    reinterpret_cast<__nv_bfloat162*>(hi)[2 * i + 0] = __nv_bfloat162(h0, h1);
    reinterpret_cast<__nv_bfloat162*>(hi)[2 * i + 1] = __nv_bfloat162(h2, h3);
    reinterpret_cast<__nv_bfloat162*>(lo)[2 * i + 0] = __nv_bfloat162(l0, l1);
    reinterpret_cast<__nv_bfloat162*>(lo)[2 * i + 1] = __nv_bfloat162(l2, l3);
    reinterpret_cast<__half2*>(f16)[2 * i + 0] = __floats2half2_rn(v.x, v.y);
    reinterpret_cast<__half2*>(f16)[2 * i + 1] = __floats2half2_rn(v.z, v.w);
}

// ===========================================================================
// 3-pass bf16 hi/lo GEMM (Q/K projections): scatter bf16 hi/lo [b,h,s,d]
// ===========================================================================
constexpr int TBM = 128, TBN = 128, TKC = 32;
constexpr int ROWB  = 80;
constexpr int TILEB = 128 * ROWB;
constexpr int STAGEB = 4 * TILEB;
constexpr int GSMEM = 2 * STAGEB;   // 81920

__device__ __forceinline__ void gemm_issue_chunk(
    const __nv_bfloat16* Ahi, const __nv_bfloat16* Alo,
    const __nv_bfloat16* Bhi, const __nv_bfloat16* Blo,
    uint32_t sb, int tid, int bm, int bn, int k0, int stage)
{
    #pragma unroll
    for (int i = 0; i < 8; i++) {
        int idx = tid + i * 256;
        int tile = idx >> 9;
        int row  = (idx >> 2) & 127;
        int c16  = idx & 3;
        const __nv_bfloat16* src;
        int grow;
        if (tile < 2) { grow = bm + row; src = (tile == 0) ? Ahi : Alo; }
        else          { grow = bn + row; src = (tile == 2) ? Bhi : Blo; }
        const char* gsrc = reinterpret_cast<const char*>(src + (size_t)grow * Dm + k0)
                           + c16 * 16;
        uint32_t dst = sb + stage * STAGEB + tile * TILEB + row * ROWB + c16 * 16;
        cp16(dst, gsrc);
    }
    CP_COMMIT();
}

__global__ __launch_bounds__(256, 2)
void gemm_mma3(const __nv_bfloat16* __restrict__ Ahi, const __nv_bfloat16* __restrict__ Alo,
               const __nv_bfloat16* __restrict__ Bhi, const __nv_bfloat16* __restrict__ Blo,
               const float* __restrict__ bias,
               __nv_bfloat16* __restrict__ Chi, __nv_bfloat16* __restrict__ Clo)
{
    extern __shared__ char smem[];
    const uint32_t sb = smem_to_u32(smem);
    const int tid = threadIdx.x;
    const int wid = tid >> 5, lane = tid & 31;
    const int bm = blockIdx.y * TBM, bn = blockIdx.x * TBN;
    const int wr = wid & 3;
    const int wc = wid >> 2;

    float acc[2][8][4];
    #pragma unroll
    for (int a = 0; a < 2; a++)
        #pragma unroll
        for (int b = 0; b < 8; b++)
            #pragma unroll
            for (int c = 0; c < 4; c++) acc[a][b][c] = 0.f;

    const uint32_t aOff = (lane % 16) * ROWB + (lane / 16) * 16;
    const uint32_t bOff = (((lane >> 4) << 3) + (lane & 7)) * ROWB + ((lane >> 3) & 1) * 16;

    gemm_issue_chunk(Ahi, Alo, Bhi, Blo, sb, tid, bm, bn, 0, 0);

    const int NCK = Dm / TKC;
    for (int ck = 0; ck < NCK; ck++) {
        const int s = ck & 1;
        if (ck + 1 < NCK) {
            gemm_issue_chunk(Ahi, Alo, Bhi, Blo, sb, tid, bm, bn, (ck + 1) * TKC, s ^ 1);
            CP_WAIT1();
        } else {
            CP_WAIT0();
        }
        __syncthreads();

        const uint32_t stg = sb + s * STAGEB;
        const uint32_t aHiB = stg + 0 * TILEB + (wr * 32) * ROWB + aOff;
        const uint32_t aLoB = stg + 1 * TILEB + (wr * 32) * ROWB + aOff;
        const uint32_t bHiB = stg + 2 * TILEB + (wc * 64) * ROWB + bOff;
        const uint32_t bLoB = stg + 3 * TILEB + (wc * 64) * ROWB + bOff;

        #pragma unroll
        for (int ks = 0; ks < 2; ks++) {
            uint32_t ah[2][4], al[2][4];
            #pragma unroll
            for (int mt = 0; mt < 2; mt++) {
                ldsm4(ah[mt], aHiB + mt * 16 * ROWB + ks * 32);
                ldsm4(al[mt], aLoB + mt * 16 * ROWB + ks * 32);
            }
            #pragma unroll
            for (int nt = 0; nt < 4; nt++) {
                uint32_t bh[4], bl[4];
                ldsm4(bh, bHiB + nt * 16 * ROWB + ks * 32);
                ldsm4(bl, bLoB + nt * 16 * ROWB + ks * 32);
                #pragma unroll
                for (int mt = 0; mt < 2; mt++) {
                    mma_bf16(acc[mt][2 * nt + 0], ah[mt], bh[0], bh[1]);
                    mma_bf16(acc[mt][2 * nt + 1], ah[mt], bh[2], bh[3]);
                    mma_bf16(acc[mt][2 * nt + 0], ah[mt], bl[0], bl[1]);
                    mma_bf16(acc[mt][2 * nt + 1], ah[mt], bl[2], bl[3]);
                    mma_bf16(acc[mt][2 * nt + 0], al[mt], bh[0], bh[1]);
                    mma_bf16(acc[mt][2 * nt + 1], al[mt], bh[2], bh[3]);
                }
            }
        }
        __syncthreads();
    }

    const int grp = lane >> 2;
    const int qid = lane & 3;
    #pragma unroll
    for (int mt = 0; mt < 2; mt++) {
        #pragma unroll
        for (int na = 0; na < 8; na++) {
            const int n0 = bn + wc * 64 + na * 8 + qid * 2;
            const float b0 = bias[n0], b1 = bias[n0 + 1];
            #pragma unroll
            for (int half = 0; half < 2; half++) {
                const int m = bm + wr * 32 + mt * 16 + grp + half * 8;
                const float v0 = acc[mt][na][2 * half + 0] + b0;
                const float v1 = acc[mt][na][2 * half + 1] + b1;
                const int b = m >> 11;
                const int sI = m & 2047;
                const int h = n0 >> 6;
                const int d = n0 & 63;
                const size_t o = ((((size_t)b * Hh + h) * Sq + sI) << 6) + d;
                __nv_bfloat16 h0 = __float2bfloat16(v0);
                __nv_bfloat16 h1 = __float2bfloat16(v1);
                __nv_bfloat16 l0 = __float2bfloat16(v0 - __bfloat162float(h0));
                __nv_bfloat16 l1 = __float2bfloat16(v1 - __bfloat162float(h1));
                *reinterpret_cast<__nv_bfloat162*>(&Chi[o]) = __nv_bfloat162(h0, h1);
                *reinterpret_cast<__nv_bfloat162*>(&Clo[o]) = __nv_bfloat162(l0, l1);
            }
        }
    }
}

// ===========================================================================
// 1-pass fp16 GEMM (V projection, output projection)
// mode 0: fp32 row-major -> C ;  mode 2: fp16 scatter [b,h,s,d] -> Cv
// ===========================================================================
constexpr int F1_STAGEB = 2 * TILEB;       // A + B
constexpr int F1_SMEM = 2 * F1_STAGEB;     // 40960

__device__ __forceinline__ void gemm_f16_issue(
    const __half* A, const __half* B,
    uint32_t sb, int tid, int bm, int bn, int k0, int stage)
{
    #pragma unroll
    for (int i = 0; i < 4; i++) {
        int idx = tid + i * 256;            // 0..1023
        int tile = idx >> 9;                // 0=A 1=B
        int row  = (idx >> 2) & 127;
        int c16  = idx & 3;
        const __half* src = tile ? B : A;
        int grow = (tile ? bn : bm) + row;
        const char* gsrc = reinterpret_cast<const char*>(src + (size_t)grow * Dm + k0)
                           + c16 * 16;
        uint32_t dst = sb + stage * F1_STAGEB + tile * TILEB + row * ROWB + c16 * 16;
        cp16(dst, gsrc);
    }
    CP_COMMIT();
}

__global__ __launch_bounds__(256, 2)
void gemm_f16k(const __half* __restrict__ A, const __half* __restrict__ B,
               const float* __restrict__ bias, float* __restrict__ C,
               __half* __restrict__ Cv, const int mode)
{
    extern __shared__ char smem[];
    const uint32_t sb = smem_to_u32(smem);
    const int tid = threadIdx.x;
    const int wid = tid >> 5, lane = tid & 31;
    const int bm = blockIdx.y * TBM, bn = blockIdx.x * TBN;
    const int wr = wid & 3;
    const int wc = wid >> 2;

    float acc[2][8][4];
    #pragma unroll
    for (int a = 0; a < 2; a++)
        #pragma unroll
        for (int b = 0; b < 8; b++)
            #pragma unroll
            for (int c = 0; c < 4; c++) acc[a][b][c] = 0.f;

    const uint32_t aOff = (lane % 16) * ROWB + (lane / 16) * 16;
    const uint32_t bOff = (((lane >> 4) << 3) + (lane & 7)) * ROWB + ((lane >> 3) & 1) * 16;

    gemm_f16_issue(A, B, sb, tid, bm, bn, 0, 0);

    const int NCK = Dm / TKC;
    for (int ck = 0; ck < NCK; ck++) {
        const int s = ck & 1;
        if (ck + 1 < NCK) {
            gemm_f16_issue(A, B, sb, tid, bm, bn, (ck + 1) * TKC, s ^ 1);
            CP_WAIT1();
        } else {
            CP_WAIT0();
        }
        __syncthreads();

        const uint32_t stg = sb + s * F1_STAGEB;
        const uint32_t aB = stg + 0 * TILEB + (wr * 32) * ROWB + aOff;
        const uint32_t bB = stg + 1 * TILEB + (wc * 64) * ROWB + bOff;

        #pragma unroll
        for (int ks = 0; ks < 2; ks++) {
            uint32_t ah[2][4];
            #pragma unroll
            for (int mt = 0; mt < 2; mt++)
                ldsm4(ah[mt], aB + mt * 16 * ROWB + ks * 32);
            #pragma unroll
            for (int nt = 0; nt < 4; nt++) {
                uint32_t bh[4];
                ldsm4(bh, bB + nt * 16 * ROWB + ks * 32);
                #pragma unroll
                for (int mt = 0; mt < 2; mt++) {
                    mma_f16(acc[mt][2 * nt + 0], ah[mt], bh[0], bh[1]);
                    mma_f16(acc[mt][2 * nt + 1], ah[mt], bh[2], bh[3]);
                }
            }
        }
        __syncthreads();
    }

    const int grp = lane >> 2;
    const int qid = lane & 3;
    #pragma unroll
    for (int mt = 0; mt < 2; mt++) {
        #pragma unroll
        for (int na = 0; na < 8; na++) {
            const int n0 = bn + wc * 64 + na * 8 + qid * 2;
            const float b0 = bias[n0], b1 = bias[n0 + 1];
            #pragma unroll
            for (int half = 0; half < 2; half++) {
                const int m = bm + wr * 32 + mt * 16 + grp + half * 8;
                const float v0 = acc[mt][na][2 * half + 0] + b0;
                const float v1 = acc[mt][na][2 * half + 1] + b1;
                if (mode == 0) {
                    *reinterpret_cast<float2*>(&C[(size_t)m * Dm + n0]) =
                        make_float2(v0, v1);
                } else {
                    const int b = m >> 11;
                    const int sI = m & 2047;
                    const int h = n0 >> 6;
                    const int d = n0 & 63;
                    const size_t o = ((((size_t)b * Hh + h) * Sq + sI) << 6) + d;
                    *reinterpret_cast<__half2*>(&Cv[o]) = __floats2half2_rn(v0, v1);
                }
            }
        }
    }
}

// ===========================================================================
// Tensor-core flash attention (QK^T bf16 hi/lo 3-pass, PV fp16 1-pass).
// Output: fp16 row-major [b*s, Dm].
// ===========================================================================
constexpr int FBQ = 128, FBK = 64;
constexpr int FROWB = 144;
constexpr int F_QH = 0;
constexpr int F_QL = F_QH + FBQ * FROWB;
constexpr int F_KH = F_QL + FBQ * FROWB;
constexpr int F_KL = F_KH + FBK * FROWB;
constexpr int F_V  = F_KL + FBK * FROWB;
constexpr int FSMEM = F_V + FBK * FROWB;     // 64512

__global__ __launch_bounds__(256, 2)
void flash_tc(const __nv_bfloat16* __restrict__ Qhi, const __nv_bfloat16* __restrict__ Qlo,
              const __nv_bfloat16* __restrict__ Khi, const __nv_bfloat16* __restrict__ Klo,
              const __half* __restrict__ Vh, __half* __restrict__ Oh)
{
    extern __shared__ char smem[];
    const uint32_t sb = smem_to_u32(smem);
    const int tid = threadIdx.x;
    const int w = tid >> 5, lane = tid & 31;
    const int grp = lane >> 2, qid = lane & 3;

    const int bh = blockIdx.y;
    const int qt = gridDim.x - 1 - blockIdx.x;
    const int q0 = qt * FBQ;
    const size_t rowbase = (size_t)bh * Sq;

    constexpr float SCALE = 0.18033688011112042f;  // (1/8) * log2(e)

    #pragma unroll
    for (int i = 0; i < 8; i++) {
        int idx = tid + i * 256;
        int arr = idx >> 10;
        int row = (idx >> 3) & 127;
        int c = idx & 7;
        const __nv_bfloat16* src = arr ? Qlo : Qhi;
        cp16(sb + (arr ? F_QL : F_QH) + row * FROWB + c * 16,
             reinterpret_cast<const char*>(src + (rowbase + q0 + row) * Dh) + c * 16);
    }
    CP_COMMIT();

    float m0 = -1e30f, m1 = -1e30f, l0 = 0.f, l1 = 0.f;
    float o[8][4];
    #pragma unroll
    for (int t = 0; t < 8; t++)
        #pragma unroll
        for (int i = 0; i < 4; i++) o[t][i] = 0.f;

    const int rw0 = q0 + w * 16;
    const uint32_t aOffQ = sb + F_QH + (w * 16 + lane % 16) * FROWB + (lane / 16) * 16;
    const uint32_t bOffK = (((lane >> 4) << 3) + (lane & 7)) * FROWB + ((lane >> 3) & 1) * 16;

    const int KT = 2 * (qt + 1);
    for (int kt = 0; kt < KT; kt++) {
        const int k0 = kt * FBK;
        #pragma unroll
        for (int i = 0; i < 6; i++) {
            int idx = tid + i * 256;
            int arr = idx >> 9;
            int row = (idx >> 3) & 63;
            int c = idx & 7;
            const char* src;
            uint32_t base;
            if (arr == 0) { src = (const char*)(Khi + (rowbase + k0 + row) * Dh); base = F_KH; }
            else if (arr == 1) { src = (const char*)(Klo + (rowbase + k0 + row) * Dh); base = F_KL; }
            else { src = (const char*)(Vh + (rowbase + k0 + row) * Dh); base = F_V; }
            cp16(sb + base + row * FROWB + c * 16, src + c * 16);
        }
        CP_COMMIT();
        CP_WAIT0();
        __syncthreads();

        if (k0 <= rw0 + 15) {
            float sc[8][4];
            #pragma unroll
            for (int t = 0; t < 8; t++)
                #pragma unroll
                for (int i = 0; i < 4; i++) sc[t][i] = 0.f;

            #pragma unroll
            for (int ks = 0; ks < 4; ks++) {
                uint32_t ah[4], al[4];
                ldsm4(ah, aOffQ + ks * 32);
                ldsm4(al, aOffQ + (F_QL - F_QH) + ks * 32);
                #pragma unroll
                for (int ntp = 0; ntp < 4; ntp++) {
                    uint32_t bh[4], bl[4];
                    uint32_t kaddr = sb + F_KH + ntp * 16 * FROWB + bOffK + ks * 32;
                    ldsm4(bh, kaddr);
                    ldsm4(bl, kaddr + (F_KL - F_KH));
                    mma_bf16(sc[2 * ntp + 0], ah, bh[0], bh[1]);
                    mma_bf16(sc[2 * ntp + 1], ah, bh[2], bh[3]);
                    mma_bf16(sc[2 * ntp + 0], ah, bl[0], bl[1]);
                    mma_bf16(sc[2 * ntp + 1], ah, bl[2], bl[3]);
                    mma_bf16(sc[2 * ntp + 0], al, bh[0], bh[1]);
                    mma_bf16(sc[2 * ntp + 1], al, bh[2], bh[3]);
                }
            }

            const bool needMask = (k0 + FBK - 1 > rw0);
            const int r0g = rw0 + grp, r1g = r0g + 8;
            #pragma unroll
            for (int t = 0; t < 8; t++) {
                #pragma unroll
                for (int i = 0; i < 4; i++) sc[t][i] *= SCALE;
                if (needMask) {
                    const int jc = k0 + t * 8 + qid * 2;
                    if (jc + 0 > r0g) sc[t][0] = -1e4f;
                    if (jc + 1 > r0g) sc[t][1] = -1e4f;
                    if (jc + 0 > r1g) sc[t][2] = -1e4f;
                    if (jc + 1 > r1g) sc[t][3] = -1e4f;
                }
            }

            float mx0 = sc[0][0], mx1 = sc[0][2];
            #pragma unroll
            for (int t = 0; t < 8; t++) {
                mx0 = fmaxf(mx0, fmaxf(sc[t][0], sc[t][1]));
                mx1 = fmaxf(mx1, fmaxf(sc[t][2], sc[t][3]));
            }
            mx0 = fmaxf(mx0, __shfl_xor_sync(0xffffffff, mx0, 1));
            mx0 = fmaxf(mx0, __shfl_xor_sync(0xffffffff, mx0, 2));
            mx1 = fmaxf(mx1, __shfl_xor_sync(0xffffffff, mx1, 1));
            mx1 = fmaxf(mx1, __shfl_xor_sync(0xffffffff, mx1, 2));
            const float nm0 = fmaxf(m0, mx0), nm1 = fmaxf(m1, mx1);
            const float f0 = exp2f(m0 - nm0), f1 = exp2f(m1 - nm1);
            m0 = nm0; m1 = nm1;

            uint32_t pp[8][2];
            float sum0 = 0.f, sum1 = 0.f;
            #pragma unroll
            for (int t = 0; t < 8; t++) {
                const float p0 = exp2f(sc[t][0] - m0);
                const float p1 = exp2f(sc[t][1] - m0);
                const float p2 = exp2f(sc[t][2] - m1);
                const float p3 = exp2f(sc[t][3] - m1);
                sum0 += p0 + p1; sum1 += p2 + p3;
                __half2 h01 = __floats2half2_rn(p0, p1);
                __half2 h23 = __floats2half2_rn(p2, p3);
                pp[t][0] = *reinterpret_cast<uint32_t*>(&h01);
                pp[t][1] = *reinterpret_cast<uint32_t*>(&h23);
            }
            sum0 += __shfl_xor_sync(0xffffffff, sum0, 1);
            sum0 += __shfl_xor_sync(0xffffffff, sum0, 2);
            sum1 += __shfl_xor_sync(0xffffffff, sum1, 1);
            sum1 += __shfl_xor_sync(0xffffffff, sum1, 2);
            l0 = l0 * f0 + sum0;
            l1 = l1 * f1 + sum1;

            #pragma unroll
            for (int t = 0; t < 8; t++) {
                o[t][0] *= f0; o[t][1] *= f0; o[t][2] *= f1; o[t][3] *= f1;
            }

            #pragma unroll
            for (int kk = 0; kk < 4; kk++) {
                uint32_t a[4] = { pp[2 * kk][0], pp[2 * kk][1],
                                  pp[2 * kk + 1][0], pp[2 * kk + 1][1] };
                #pragma unroll
                for (int ntp = 0; ntp < 4; ntp++) {
                    uint32_t bv[4];
                    ldsm4t(bv, sb + F_V + (kk * 16 + (lane & 15)) * FROWB
                               + (2 * ntp + (lane >> 4)) * 16);
                    mma_f16(o[2 * ntp + 0], a, bv[0], bv[1]);
                    mma_f16(o[2 * ntp + 1], a, bv[2], bv[3]);
                }
            }
        }
        __syncthreads();
    }

    // epilogue: fp16 row-major [b*s, Dm]
    const int b = bh >> 4, h = bh & 15;
    const float inv0 = 1.0f / l0, inv1 = 1.0f / l1;
    const size_t row0 = ((size_t)b * Sq + (q0 + w * 16 + grp)) * Dm + h * Dh;
    const size_t row1 = row0 + 8 * Dm;
    #pragma unroll
    for (int t = 0; t < 8; t++) {
        const int col = t * 8 + qid * 2;
        *reinterpret_cast<__half2*>(&Oh[row0 + col]) =
            __floats2half2_rn(o[t][0] * inv0, o[t][1] * inv0);
        *reinterpret_cast<__half2*>(&Oh[row1 + col]) =
            __floats2half2_rn(o[t][2] * inv1, o[t][3] * inv1);
    }
}

// ===========================================================================
extern "C" void kernel_launch(void* const* d_in, const int* in_sizes, int n_in,
                              void* d_out, int out_size)
{
    const float* x  = (const float*)d_in[0];
    const float* Wq = (const float*)d_in[2];
    const float* bq = (const float*)d_in[3];
    const float* Wk = (const float*)d_in[4];
    const float* bk = (const float*)d_in[5];
    const float* Wv = (const float*)d_in[6];
    const float* bv = (const float*)d_in[7];
    const float* Wo = (const float*)d_in[8];
    const float* bo = (const float*)d_in[9];
    float* out = (float*)d_out;

    __nv_bfloat16 *xhi, *xlo, *whi, *wlo, *qhi, *qlo, *khi, *klo;
    __half *xh, *wh16, *vh;
    cudaGetSymbolAddress((void**)&xhi, g_xhi);
    cudaGetSymbolAddress((void**)&xlo, g_xlo);
    cudaGetSymbolAddress((void**)&xh,  g_xh);
    cudaGetSymbolAddress((void**)&whi, g_whi);
    cudaGetSymbolAddress((void**)&wlo, g_wlo);
    cudaGetSymbolAddress((void**)&wh16, g_wh16);
    cudaGetSymbolAddress((void**)&qhi, g_Qhi);
    cudaGetSymbolAddress((void**)&qlo, g_Qlo);
    cudaGetSymbolAddress((void**)&khi, g_Khi);
    cudaGetSymbolAddress((void**)&klo, g_Klo);
    cudaGetSymbolAddress((void**)&vh, g_Vh);

    static bool attr_set = false;
    if (!attr_set) {
        cudaFuncSetAttribute(gemm_mma3, cudaFuncAttributeMaxDynamicSharedMemorySize, GSMEM);
        cudaFuncSetAttribute(gemm_f16k, cudaFuncAttributeMaxDynamicSharedMemorySize, F1_SMEM);
        cudaFuncSetAttribute(flash_tc, cudaFuncAttributeMaxDynamicSharedMemorySize, FSMEM);
        attr_set = true;
    }

    const size_t wN = (size_t)Dm * Dm;
    const int xn4 = Mr * Dm / 4;
    const int wn4 = (int)(wN / 4);

    // x -> bf16 hi/lo + fp16
    cvt_all<<<(xn4 + 255) / 256, 256>>>(x, xhi, xlo, xh, xn4);
    // Wq, Wk -> bf16 hi/lo
    cvt_hilo<<<(wn4 + 255) / 256, 256>>>(Wq, whi + 0 * wN, wlo + 0 * wN, wn4);
    cvt_hilo<<<(wn4 + 255) / 256, 256>>>(Wk, whi + 1 * wN, wlo + 1 * wN, wn4);
    // Wv, Wo -> fp16
    cvt_f16<<<(wn4 + 255) / 256, 256>>>(Wv, wh16 + 0 * wN, wn4);
    cvt_f16<<<(wn4 + 255) / 256, 256>>>(Wo, wh16 + 1 * wN, wn4);

    const dim3 ggrid(Dm / TBN, Mr / TBM);   // (8, 64)
    gemm_mma3<<<ggrid, 256, GSMEM>>>(xhi, xlo, whi + 0 * wN, wlo + 0 * wN, bq, qhi, qlo);
    gemm_mma3<<<ggrid, 256, GSMEM>>>(xhi, xlo, whi + 1 * wN, wlo + 1 * wN, bk, khi, klo);
    gemm_f16k<<<ggrid, 256, F1_SMEM>>>(xh, wh16 + 0 * wN, bv, nullptr, vh, 2);

    // flash writes fp16 O over xh (x fp16 no longer needed)
    flash_tc<<<dim3(Sq / FBQ, Bz * Hh), 256, FSMEM>>>(qhi, qlo, khi, klo, vh, xh);

    gemm_f16k<<<ggrid, 256, F1_SMEM>>>(xh, wh16 + 1 * wN, bo, out, nullptr, 0);
}

// round 6
// speedup vs baseline: 5.7298x; 1.3361x over previous
#include <cuda_runtime.h>
#include <cuda_fp16.h>
#include <cstdint>
#include <math.h>

// Problem constants
constexpr int Bz = 4;
constexpr int Sq = 2048;
constexpr int Dm = 1024;
constexpr int Hh = 16;
constexpr int Dh = 64;
constexpr int Mr = Bz * Sq;    // 8192

// Scratch (allocation-free rule: __device__ globals)
__device__ __half g_xh[(size_t)Mr * Dm];      // x fp16 hi; later reused for attn-out
__device__ __half g_xl[(size_t)Mr * Dm];      // x fp16 lo residual
__device__ __half g_w[4][(size_t)Dm * Dm];    // Wq, Wk, Wv, Wo fp16
__device__ __half g_Qh[(size_t)Mr * Dm];
__device__ __half g_Kh[(size_t)Mr * Dm];
__device__ __half g_Vh[(size_t)Mr * Dm];

// ===========================================================================
// PTX helpers
// ===========================================================================
__device__ __forceinline__ uint32_t smem_to_u32(const void* p) {
    uint32_t a;
    asm("{ .reg .u64 t; cvta.to.shared.u64 t, %1; cvt.u32.u64 %0, t; }"
        : "=r"(a) : "l"(p));
    return a;
}
__device__ __forceinline__ void cp16(uint32_t dst, const void* src) {
    asm volatile("cp.async.cg.shared.global [%0], [%1], 16;" :: "r"(dst), "l"(src));
}
#define CP_COMMIT() asm volatile("cp.async.commit_group;" ::: "memory")
#define CP_WAIT1()  asm volatile("cp.async.wait_group 1;" ::: "memory")
#define CP_WAIT0()  asm volatile("cp.async.wait_group 0;" ::: "memory")

__device__ __forceinline__ void ldsm4(uint32_t* r, uint32_t addr) {
    asm volatile("ldmatrix.sync.aligned.m8n8.x4.shared.b16 {%0,%1,%2,%3}, [%4];"
        : "=r"(r[0]), "=r"(r[1]), "=r"(r[2]), "=r"(r[3]) : "r"(addr));
}
__device__ __forceinline__ void ldsm4t(uint32_t* r, uint32_t addr) {
    asm volatile("ldmatrix.sync.aligned.m8n8.x4.trans.shared.b16 {%0,%1,%2,%3}, [%4];"
        : "=r"(r[0]), "=r"(r[1]), "=r"(r[2]), "=r"(r[3]) : "r"(addr));
}
__device__ __forceinline__ void mma_f16(float* d, const uint32_t* a,
                                        uint32_t b0, uint32_t b1) {
    asm volatile(
        "mma.sync.aligned.m16n8k16.row.col.f32.f16.f16.f32 "
        "{%0,%1,%2,%3}, {%4,%5,%6,%7}, {%8,%9}, {%0,%1,%2,%3};"
        : "+f"(d[0]), "+f"(d[1]), "+f"(d[2]), "+f"(d[3])
        : "r"(a[0]), "r"(a[1]), "r"(a[2]), "r"(a[3]), "r"(b0), "r"(b1));
}

// ===========================================================================
// Conversion kernels (pure bandwidth)
// ===========================================================================
__global__ __launch_bounds__(256)
void cvt_f16(const float* __restrict__ src, __half* __restrict__ dst, int n4)
{
    int i = blockIdx.x * blockDim.x + threadIdx.x;
    if (i >= n4) return;
    float4 v = reinterpret_cast<const float4*>(src)[i];
    reinterpret_cast<__half2*>(dst)[2 * i + 0] = __floats2half2_rn(v.x, v.y);
    reinterpret_cast<__half2*>(dst)[2 * i + 1] = __floats2half2_rn(v.z, v.w);
}

// x -> fp16 hi + fp16 lo residual
__global__ __launch_bounds__(256)
void cvt_xhl(const float* __restrict__ src, __half* __restrict__ hi,
             __half* __restrict__ lo, int n4)
{
    int i = blockIdx.x * blockDim.x + threadIdx.x;
    if (i >= n4) return;
    float4 v = reinterpret_cast<const float4*>(src)[i];
    __half h0 = __float2half_rn(v.x);
    __half h1 = __float2half_rn(v.y);
    __half h2 = __float2half_rn(v.z);
    __half h3 = __float2half_rn(v.w);
    __half l0 = __float2half_rn(v.x - __half2float(h0));
    __half l1 = __float2half_rn(v.y - __half2float(h1));
    __half l2 = __float2half_rn(v.z - __half2float(h2));
    __half l3 = __float2half_rn(v.w - __half2float(h3));
    reinterpret_cast<__half2*>(hi)[2 * i + 0] = __half2(h0, h1);
    reinterpret_cast<__half2*>(hi)[2 * i + 1] = __half2(h2, h3);
    reinterpret_cast<__half2*>(lo)[2 * i + 0] = __half2(l0, l1);
    reinterpret_cast<__half2*>(lo)[2 * i + 1] = __half2(l2, l3);
}

// ===========================================================================
// fp16 GEMM: C[M,N] = (A (+ Al)) [M,K] * B[N,K]^T + bias
// TWO=1: A given as hi+lo fp16 pair (2-pass, x kept exact to ~2^-21)
// mode 0: fp32 row-major C ; mode 2: fp16 scatter [b,h,s,d]
// ===========================================================================
constexpr int TBM = 128, TBN = 128, TKC = 32;
constexpr int ROWB  = 80;            // 32 fp16 = 64B + 16B pad
constexpr int TILEB = 128 * ROWB;    // 10240

template<int TWO>
__device__ __forceinline__ void gemm_issue(
    const __half* A, const __half* Al, const __half* B,
    uint32_t sb, int tid, int bm, int bn, int k0, int stage)
{
    constexpr int NT = 2 + TWO;
    #pragma unroll
    for (int i = 0; i < 2 * NT; i++) {
        int idx = tid + i * 256;
        int tile = idx >> 9;              // 0=A, (1=Al), last=B
        int row  = (idx >> 2) & 127;
        int c16  = idx & 3;
        const __half* src;
        int grow;
        if (tile == NT - 1) { src = B; grow = bn + row; }
        else if (tile == 0) { src = A;  grow = bm + row; }
        else                { src = Al; grow = bm + row; }
        const char* gsrc = reinterpret_cast<const char*>(src + (size_t)grow * Dm + k0)
                           + c16 * 16;
        uint32_t dst = sb + stage * (NT * TILEB) + tile * TILEB + row * ROWB + c16 * 16;
        cp16(dst, gsrc);
    }
    CP_COMMIT();
}

template<int TWO>
__global__ __launch_bounds__(256, 2)
void gemm_h(const __half* __restrict__ A, const __half* __restrict__ Al,
            const __half* __restrict__ B, const float* __restrict__ bias,
            float* __restrict__ C, __half* __restrict__ Ch, const int mode)
{
    constexpr int NT = 2 + TWO;
    constexpr int STG = NT * TILEB;
    extern __shared__ char smem[];
    const uint32_t sb = smem_to_u32(smem);
    const int tid = threadIdx.x;
    const int wid = tid >> 5, lane = tid & 31;
    const int bm = blockIdx.y * TBM, bn = blockIdx.x * TBN;
    const int wr = wid & 3;
    const int wc = wid >> 2;

    float acc[2][8][4];
    #pragma unroll
    for (int a = 0; a < 2; a++)
        #pragma unroll
        for (int b = 0; b < 8; b++)
            #pragma unroll
            for (int c = 0; c < 4; c++) acc[a][b][c] = 0.f;

    const uint32_t aOff = (lane % 16) * ROWB + (lane / 16) * 16;
    const uint32_t bOff = (((lane >> 4) << 3) + (lane & 7)) * ROWB + ((lane >> 3) & 1) * 16;

    gemm_issue<TWO>(A, Al, B, sb, tid, bm, bn, 0, 0);

    const int NCK = Dm / TKC;
    for (int ck = 0; ck < NCK; ck++) {
        const int s = ck & 1;
        if (ck + 1 < NCK) {
            gemm_issue<TWO>(A, Al, B, sb, tid, bm, bn, (ck + 1) * TKC, s ^ 1);
            CP_WAIT1();
        } else {
            CP_WAIT0();
        }
        __syncthreads();

        const uint32_t stg = sb + s * STG;
        const uint32_t aB  = stg + (wr * 32) * ROWB + aOff;
        const uint32_t bB  = stg + (NT - 1) * TILEB + (wc * 64) * ROWB + bOff;

        #pragma unroll
        for (int ks = 0; ks < 2; ks++) {
            uint32_t ah[2][4], al[2][4];
            #pragma unroll
            for (int mt = 0; mt < 2; mt++) {
                ldsm4(ah[mt], aB + mt * 16 * ROWB + ks * 32);
                if (TWO) ldsm4(al[mt], aB + TILEB + mt * 16 * ROWB + ks * 32);
            }
            #pragma unroll
            for (int nt = 0; nt < 4; nt++) {
                uint32_t bh[4];
                ldsm4(bh, bB + nt * 16 * ROWB + ks * 32);
                #pragma unroll
                for (int mt = 0; mt < 2; mt++) {
                    mma_f16(acc[mt][2 * nt + 0], ah[mt], bh[0], bh[1]);
                    mma_f16(acc[mt][2 * nt + 1], ah[mt], bh[2], bh[3]);
                    if (TWO) {
                        mma_f16(acc[mt][2 * nt + 0], al[mt], bh[0], bh[1]);
                        mma_f16(acc[mt][2 * nt + 1], al[mt], bh[2], bh[3]);
                    }
                }
            }
        }
        __syncthreads();
    }

    const int grp = lane >> 2;
    const int qid = lane & 3;
    #pragma unroll
    for (int mt = 0; mt < 2; mt++) {
        #pragma unroll
        for (int na = 0; na < 8; na++) {
            const int n0 = bn + wc * 64 + na * 8 + qid * 2;
            const float b0 = bias[n0], b1 = bias[n0 + 1];
            #pragma unroll
            for (int half = 0; half < 2; half++) {
                const int m = bm + wr * 32 + mt * 16 + grp + half * 8;
                const float v0 = acc[mt][na][2 * half + 0] + b0;
                const float v1 = acc[mt][na][2 * half + 1] + b1;
                if (mode == 0) {
                    *reinterpret_cast<float2*>(&C[(size_t)m * Dm + n0]) =
                        make_float2(v0, v1);
                } else {
                    const int b = m >> 11;
                    const int sI = m & 2047;
                    const int h = n0 >> 6;
                    const int d = n0 & 63;
                    const size_t o = ((((size_t)b * Hh + h) * Sq + sI) << 6) + d;
                    *reinterpret_cast<__half2*>(&Ch[o]) = __floats2half2_rn(v0, v1);
                }
            }
        }
    }
}

// ===========================================================================
// Tensor-core flash attention (1-pass fp16 QK^T, 1-pass fp16 PV)
// Output: fp16 row-major [b*s, Dm].
// ===========================================================================
constexpr int FBQ = 128, FBK = 64;
constexpr int FROWB = 144;                 // 64 fp16 = 128B + 16B pad
constexpr int F_Q = 0;
constexpr int F_K = F_Q + FBQ * FROWB;     // 18432
constexpr int F_V = F_K + FBK * FROWB;     // 27648
constexpr int FSMEM = F_V + FBK * FROWB;   // 36864

__global__ __launch_bounds__(256, 2)
void flash_tc(const __half* __restrict__ Qh, const __half* __restrict__ Kh,
              const __half* __restrict__ Vh, __half* __restrict__ Oh)
{
    extern __shared__ char smem[];
    const uint32_t sb = smem_to_u32(smem);
    const int tid = threadIdx.x;
    const int w = tid >> 5, lane = tid & 31;
    const int grp = lane >> 2, qid = lane & 3;

    const int bh = blockIdx.y;
    const int qt = gridDim.x - 1 - blockIdx.x;   // big tiles first
    const int q0 = qt * FBQ;
    const size_t rowbase = (size_t)bh * Sq;

    constexpr float SCALE = 0.18033688011112042f;  // (1/8) * log2(e)

    // load Q tile: 128 rows x 64B = 1024 chunks, 4/thread
    #pragma unroll
    for (int i = 0; i < 4; i++) {
        int idx = tid + i * 256;
        int row = idx >> 3;
        int c = idx & 7;
        cp16(sb + F_Q + row * FROWB + c * 16,
             reinterpret_cast<const char*>(Qh + (rowbase + q0 + row) * Dh) + c * 16);
    }
    CP_COMMIT();

    float m0 = -1e30f, m1 = -1e30f, l0 = 0.f, l1 = 0.f;
    float o[8][4];
    #pragma unroll
    for (int t = 0; t < 8; t++)
        #pragma unroll
        for (int i = 0; i < 4; i++) o[t][i] = 0.f;

    const int rw0 = q0 + w * 16;
    const uint32_t aOffQ = sb + F_Q + (w * 16 + lane % 16) * FROWB + (lane / 16) * 16;
    const uint32_t bOffK = (((lane >> 4) << 3) + (lane & 7)) * FROWB + ((lane >> 3) & 1) * 16;

    const int KT = 2 * (qt + 1);
    for (int kt = 0; kt < KT; kt++) {
        const int k0 = kt * FBK;
        // load K + V tiles: 2 * 64 rows x 64B = 1024 chunks, 4/thread
        #pragma unroll
        for (int i = 0; i < 4; i++) {
            int idx = tid + i * 256;
            int arr = idx >> 9;            // 0=K 1=V
            int row = (idx >> 3) & 63;
            int c = idx & 7;
            const char* src = arr
                ? (const char*)(Vh + (rowbase + k0 + row) * Dh)
                : (const char*)(Kh + (rowbase + k0 + row) * Dh);
            cp16(sb + (arr ? F_V : F_K) + row * FROWB + c * 16, src + c * 16);
        }
        CP_COMMIT();
        CP_WAIT0();
        __syncthreads();

        if (k0 <= rw0 + 15) {
            // ---- S = Q K^T, 1-pass fp16 ----
            float sc[8][4];
            #pragma unroll
            for (int t = 0; t < 8; t++)
                #pragma unroll
                for (int i = 0; i < 4; i++) sc[t][i] = 0.f;

            #pragma unroll
            for (int ks = 0; ks < 4; ks++) {
                uint32_t ah[4];
                ldsm4(ah, aOffQ + ks * 32);
                #pragma unroll
                for (int ntp = 0; ntp < 4; ntp++) {
                    uint32_t bh[4];
                    ldsm4(bh, sb + F_K + ntp * 16 * FROWB + bOffK + ks * 32);
                    mma_f16(sc[2 * ntp + 0], ah, bh[0], bh[1]);
                    mma_f16(sc[2 * ntp + 1], ah, bh[2], bh[3]);
                }
            }

            const bool needMask = (k0 + FBK - 1 > rw0);
            const int r0g = rw0 + grp, r1g = r0g + 8;
            #pragma unroll
            for (int t = 0; t < 8; t++) {
                #pragma unroll
                for (int i = 0; i < 4; i++) sc[t][i] *= SCALE;
                if (needMask) {
                    const int jc = k0 + t * 8 + qid * 2;
                    if (jc + 0 > r0g) sc[t][0] = -1e4f;
                    if (jc + 1 > r0g) sc[t][1] = -1e4f;
                    if (jc + 0 > r1g) sc[t][2] = -1e4f;
                    if (jc + 1 > r1g) sc[t][3] = -1e4f;
                }
            }

            float mx0 = sc[0][0], mx1 = sc[0][2];
            #pragma unroll
            for (int t = 0; t < 8; t++) {
                mx0 = fmaxf(mx0, fmaxf(sc[t][0], sc[t][1]));
                mx1 = fmaxf(mx1, fmaxf(sc[t][2], sc[t][3]));
            }
            mx0 = fmaxf(mx0, __shfl_xor_sync(0xffffffff, mx0, 1));
            mx0 = fmaxf(mx0, __shfl_xor_sync(0xffffffff, mx0, 2));
            mx1 = fmaxf(mx1, __shfl_xor_sync(0xffffffff, mx1, 1));
            mx1 = fmaxf(mx1, __shfl_xor_sync(0xffffffff, mx1, 2));
            const float nm0 = fmaxf(m0, mx0), nm1 = fmaxf(m1, mx1);
            const float f0 = exp2f(m0 - nm0), f1 = exp2f(m1 - nm1);
            m0 = nm0; m1 = nm1;

            uint32_t pp[8][2];
            float sum0 = 0.f, sum1 = 0.f;
            #pragma unroll
            for (int t = 0; t < 8; t++) {
                const float p0 = exp2f(sc[t][0] - m0);
                const float p1 = exp2f(sc[t][1] - m0);
                const float p2 = exp2f(sc[t][2] - m1);
                const float p3 = exp2f(sc[t][3] - m1);
                sum0 += p0 + p1; sum1 += p2 + p3;
                __half2 h01 = __floats2half2_rn(p0, p1);
                __half2 h23 = __floats2half2_rn(p2, p3);
                pp[t][0] = *reinterpret_cast<uint32_t*>(&h01);
                pp[t][1] = *reinterpret_cast<uint32_t*>(&h23);
            }
            sum0 += __shfl_xor_sync(0xffffffff, sum0, 1);
            sum0 += __shfl_xor_sync(0xffffffff, sum0, 2);
            sum1 += __shfl_xor_sync(0xffffffff, sum1, 1);
            sum1 += __shfl_xor_sync(0xffffffff, sum1, 2);
            l0 = l0 * f0 + sum0;
            l1 = l1 * f1 + sum1;

            #pragma unroll
            for (int t = 0; t < 8; t++) {
                o[t][0] *= f0; o[t][1] *= f0; o[t][2] *= f1; o[t][3] *= f1;
            }

            // ---- O += P * V (fp16, P in regs, V via ldmatrix.trans) ----
            #pragma unroll
            for (int kk = 0; kk < 4; kk++) {
                uint32_t a[4] = { pp[2 * kk][0], pp[2 * kk][1],
                                  pp[2 * kk + 1][0], pp[2 * kk + 1][1] };
                #pragma unroll
                for (int ntp = 0; ntp < 4; ntp++) {
                    uint32_t bv[4];
                    ldsm4t(bv, sb + F_V + (kk * 16 + (lane & 15)) * FROWB
                               + (2 * ntp + (lane >> 4)) * 16);
                    mma_f16(o[2 * ntp + 0], a, bv[0], bv[1]);
                    mma_f16(o[2 * ntp + 1], a, bv[2], bv[3]);
                }
            }
        }
        __syncthreads();
    }

    // epilogue: fp16 row-major [b*s, Dm]
    const int b = bh >> 4, h = bh & 15;
    const float inv0 = 1.0f / l0, inv1 = 1.0f / l1;
    const size_t row0 = ((size_t)b * Sq + (q0 + w * 16 + grp)) * Dm + h * Dh;
    const size_t row1 = row0 + 8 * Dm;
    #pragma unroll
    for (int t = 0; t < 8; t++) {
        const int col = t * 8 + qid * 2;
        *reinterpret_cast<__half2*>(&Oh[row0 + col]) =
            __floats2half2_rn(o[t][0] * inv0, o[t][1] * inv0);
        *reinterpret_cast<__half2*>(&Oh[row1 + col]) =
            __floats2half2_rn(o[t][2] * inv1, o[t][3] * inv1);
    }
}

// ===========================================================================
extern "C" void kernel_launch(void* const* d_in, const int* in_sizes, int n_in,
                              void* d_out, int out_size)
{
    const float* x  = (const float*)d_in[0];
    const float* Wq = (const float*)d_in[2];
    const float* bq = (const float*)d_in[3];
    const float* Wk = (const float*)d_in[4];
    const float* bk = (const float*)d_in[5];
    const float* Wv = (const float*)d_in[6];
    const float* bv = (const float*)d_in[7];
    const float* Wo = (const float*)d_in[8];
    const float* bo = (const float*)d_in[9];
    float* out = (float*)d_out;

    __half *xh, *xl, *wptr, *qh, *kh, *vh;
    cudaGetSymbolAddress((void**)&xh, g_xh);
    cudaGetSymbolAddress((void**)&xl, g_xl);
    cudaGetSymbolAddress((void**)&wptr, g_w);
    cudaGetSymbolAddress((void**)&qh, g_Qh);
    cudaGetSymbolAddress((void**)&kh, g_Kh);
    cudaGetSymbolAddress((void**)&vh, g_Vh);

    constexpr int GS2 = 2 * 3 * TILEB;   // 2-pass: A,Al,B double-buffered = 61440
    constexpr int GS1 = 2 * 2 * TILEB;   // 1-pass: A,B double-buffered = 40960

    static bool attr_set = false;
    if (!attr_set) {
        cudaFuncSetAttribute(gemm_h<1>, cudaFuncAttributeMaxDynamicSharedMemorySize, GS2);
        cudaFuncSetAttribute(gemm_h<0>, cudaFuncAttributeMaxDynamicSharedMemorySize, GS1);
        cudaFuncSetAttribute(flash_tc, cudaFuncAttributeMaxDynamicSharedMemorySize, FSMEM);
        attr_set = true;
    }

    const size_t wN = (size_t)Dm * Dm;
    const int xn4 = Mr * Dm / 4;
    const int wn4 = (int)(wN / 4);

    // conversions
    cvt_xhl<<<(xn4 + 255) / 256, 256>>>(x, xh, xl, xn4);
    const float* Ws[4] = {Wq, Wk, Wv, Wo};
    for (int i = 0; i < 4; i++)
        cvt_f16<<<(wn4 + 255) / 256, 256>>>(Ws[i], wptr + i * wN, wn4);

    const dim3 ggrid(Dm / TBN, Mr / TBM);   // (8, 64)
    // Q, K projections: 2-pass (x exact via hi/lo), fp16 scatter
    gemm_h<1><<<ggrid, 256, GS2>>>(xh, xl, wptr + 0 * wN, bq, nullptr, qh, 2);
    gemm_h<1><<<ggrid, 256, GS2>>>(xh, xl, wptr + 1 * wN, bk, nullptr, kh, 2);
    // V projection: 1-pass
    gemm_h<0><<<ggrid, 256, GS1>>>(xh, nullptr, wptr + 2 * wN, bv, nullptr, vh, 2);

    // flash writes fp16 O over xh
    flash_tc<<<dim3(Sq / FBQ, Bz * Hh), 256, FSMEM>>>(qh, kh, vh, xh);

    // output projection: 1-pass, fp32 out
    gemm_h<0><<<ggrid, 256, GS1>>>(xh, nullptr, wptr + 3 * wN, bo, out, nullptr, 0);
}

// round 7
// speedup vs baseline: 7.5735x; 1.3218x over previous
#include <cuda_runtime.h>
#include <cuda_fp16.h>
#include <cstdint>
#include <math.h>

// Problem constants
constexpr int Bz = 4;
constexpr int Sq = 2048;
constexpr int Dm = 1024;
constexpr int Hh = 16;
constexpr int Dh = 64;
constexpr int Mr = Bz * Sq;    // 8192

// Scratch (allocation-free rule: __device__ globals)
__device__ __half g_xh[(size_t)Mr * Dm];      // x fp16; later reused for attn-out
__device__ __half g_w[4][(size_t)Dm * Dm];    // Wq, Wk, Wv, Wo fp16 (contiguous)
__device__ __half g_Qh[(size_t)Mr * Dm];
__device__ __half g_Kh[(size_t)Mr * Dm];
__device__ __half g_Vh[(size_t)Mr * Dm];

// ===========================================================================
// PTX helpers
// ===========================================================================
__device__ __forceinline__ uint32_t smem_to_u32(const void* p) {
    uint32_t a;
    asm("{ .reg .u64 t; cvta.to.shared.u64 t, %1; cvt.u32.u64 %0, t; }"
        : "=r"(a) : "l"(p));
    return a;
}
__device__ __forceinline__ void cp16(uint32_t dst, const void* src) {
    asm volatile("cp.async.cg.shared.global [%0], [%1], 16;" :: "r"(dst), "l"(src));
}
#define CP_COMMIT() asm volatile("cp.async.commit_group;" ::: "memory")
#define CP_WAIT1()  asm volatile("cp.async.wait_group 1;" ::: "memory")
#define CP_WAIT0()  asm volatile("cp.async.wait_group 0;" ::: "memory")

__device__ __forceinline__ void ldsm4(uint32_t* r, uint32_t addr) {
    asm volatile("ldmatrix.sync.aligned.m8n8.x4.shared.b16 {%0,%1,%2,%3}, [%4];"
        : "=r"(r[0]), "=r"(r[1]), "=r"(r[2]), "=r"(r[3]) : "r"(addr));
}
__device__ __forceinline__ void ldsm4t(uint32_t* r, uint32_t addr) {
    asm volatile("ldmatrix.sync.aligned.m8n8.x4.trans.shared.b16 {%0,%1,%2,%3}, [%4];"
        : "=r"(r[0]), "=r"(r[1]), "=r"(r[2]), "=r"(r[3]) : "r"(addr));
}
__device__ __forceinline__ void mma_f16(float* d, const uint32_t* a,
                                        uint32_t b0, uint32_t b1) {
    asm volatile(
        "mma.sync.aligned.m16n8k16.row.col.f32.f16.f16.f32 "
        "{%0,%1,%2,%3}, {%4,%5,%6,%7}, {%8,%9}, {%0,%1,%2,%3};"
        : "+f"(d[0]), "+f"(d[1]), "+f"(d[2]), "+f"(d[3])
        : "r"(a[0]), "r"(a[1]), "r"(a[2]), "r"(a[3]), "r"(b0), "r"(b1));
}

// ===========================================================================
// Conversion kernels (pure bandwidth)
// ===========================================================================
__global__ __launch_bounds__(256)
void cvt_f16(const float* __restrict__ src, __half* __restrict__ dst, int n4)
{
    int i = blockIdx.x * blockDim.x + threadIdx.x;
    if (i >= n4) return;
    float4 v = reinterpret_cast<const float4*>(src)[i];
    reinterpret_cast<__half2*>(dst)[2 * i + 0] = __floats2half2_rn(v.x, v.y);
    reinterpret_cast<__half2*>(dst)[2 * i + 1] = __floats2half2_rn(v.z, v.w);
}

// 4 weights in one launch (blockIdx.y selects source)
__global__ __launch_bounds__(256)
void cvt_w4(const float* __restrict__ w0, const float* __restrict__ w1,
            const float* __restrict__ w2, const float* __restrict__ w3,
            __half* __restrict__ dst, int n4)
{
    int i = blockIdx.x * blockDim.x + threadIdx.x;
    if (i >= n4) return;
    const float* srcs[4] = {w0, w1, w2, w3};
    const float* src = srcs[blockIdx.y];
    __half* d = dst + (size_t)blockIdx.y * n4 * 4;
    float4 v = reinterpret_cast<const float4*>(src)[i];
    reinterpret_cast<__half2*>(d)[2 * i + 0] = __floats2half2_rn(v.x, v.y);
    reinterpret_cast<__half2*>(d)[2 * i + 1] = __floats2half2_rn(v.z, v.w);
}

// ===========================================================================
// Shared GEMM pieces: 128x128x32 tiles, 8 warps, A+B double-buffered cp.async
// ===========================================================================
constexpr int TBM = 128, TBN = 128, TKC = 32;
constexpr int ROWB  = 80;            // 32 fp16 = 64B + 16B pad
constexpr int TILEB = 128 * ROWB;    // 10240
constexpr int GSTG  = 2 * TILEB;     // A+B per stage
constexpr int GSMEM = 2 * GSTG;      // 40960

__device__ __forceinline__ void gemm_issue(
    const __half* A, const __half* B,
    uint32_t sb, int tid, int bm, int bn, int k0, int stage)
{
    #pragma unroll
    for (int i = 0; i < 4; i++) {
        int idx = tid + i * 256;
        int tile = idx >> 9;              // 0=A 1=B
        int row  = (idx >> 2) & 127;
        int c16  = idx & 3;
        const __half* src = tile ? B : A;
        int grow = (tile ? bn : bm) + row;
        const char* gsrc = reinterpret_cast<const char*>(src + (size_t)grow * Dm + k0)
                           + c16 * 16;
        uint32_t dst = sb + stage * GSTG + tile * TILEB + row * ROWB + c16 * 16;
        cp16(dst, gsrc);
    }
    CP_COMMIT();
}

// Mainloop shared by both GEMMs: fills acc[2][8][4]
__device__ __forceinline__ void gemm_mainloop(
    const __half* A, const __half* B, uint32_t sb, int tid,
    int bm, int bn, int wr, int wc, int lane, float acc[2][8][4])
{
    const uint32_t aOff = (lane % 16) * ROWB + (lane / 16) * 16;
    const uint32_t bOff = (((lane >> 4) << 3) + (lane & 7)) * ROWB + ((lane >> 3) & 1) * 16;

    gemm_issue(A, B, sb, tid, bm, bn, 0, 0);

    const int NCK = Dm / TKC;
    for (int ck = 0; ck < NCK; ck++) {
        const int s = ck & 1;
        if (ck + 1 < NCK) {
            gemm_issue(A, B, sb, tid, bm, bn, (ck + 1) * TKC, s ^ 1);
            CP_WAIT1();
        } else {
            CP_WAIT0();
        }
        __syncthreads();

        const uint32_t stg = sb + s * GSTG;
        const uint32_t aB  = stg + (wr * 32) * ROWB + aOff;
        const uint32_t bB  = stg + TILEB + (wc * 64) * ROWB + bOff;

        #pragma unroll
        for (int ks = 0; ks < 2; ks++) {
            uint32_t ah[2][4];
            #pragma unroll
            for (int mt = 0; mt < 2; mt++)
                ldsm4(ah[mt], aB + mt * 16 * ROWB + ks * 32);
            #pragma unroll
            for (int nt = 0; nt < 4; nt++) {
                uint32_t bh[4];
                ldsm4(bh, bB + nt * 16 * ROWB + ks * 32);
                #pragma unroll
                for (int mt = 0; mt < 2; mt++) {
                    mma_f16(acc[mt][2 * nt + 0], ah[mt], bh[0], bh[1]);
                    mma_f16(acc[mt][2 * nt + 1], ah[mt], bh[2], bh[3]);
                }
            }
        }
        __syncthreads();
    }
}

// ---------------------------------------------------------------------------
// Fused QKV projection: B = packed [Wq;Wk;Wv] (3072 rows). fp16 scatter.
// ---------------------------------------------------------------------------
__global__ __launch_bounds__(256, 2)
void gemm_qkv(const __half* __restrict__ A, const __half* __restrict__ Bw,
              const float* __restrict__ bq, const float* __restrict__ bk,
              const float* __restrict__ bv,
              __half* __restrict__ Qh, __half* __restrict__ Kh,
              __half* __restrict__ Vh)
{
    extern __shared__ char smem[];
    const uint32_t sb = smem_to_u32(smem);
    const int tid = threadIdx.x;
    const int wid = tid >> 5, lane = tid & 31;
    const int bm = blockIdx.y * TBM, bn = blockIdx.x * TBN;   // bn in [0,3072)
    const int wr = wid & 3, wc = wid >> 2;

    float acc[2][8][4];
    #pragma unroll
    for (int a = 0; a < 2; a++)
        #pragma unroll
        for (int b = 0; b < 8; b++)
            #pragma unroll
            for (int c = 0; c < 4; c++) acc[a][b][c] = 0.f;

    gemm_mainloop(A, Bw, sb, tid, bm, bn, wr, wc, lane, acc);

    // whole CTA lies in one of Q/K/V (bn multiple of 128, matrices 1024-wide)
    const int sel = bn >> 10;
    const int bnl = bn & 1023;
    const float* bias = (sel == 0) ? bq : (sel == 1) ? bk : bv;
    __half* dst = (sel == 0) ? Qh : (sel == 1) ? Kh : Vh;

    const int grp = lane >> 2, qid = lane & 3;
    #pragma unroll
    for (int mt = 0; mt < 2; mt++) {
        #pragma unroll
        for (int na = 0; na < 8; na++) {
            const int n0 = bnl + wc * 64 + na * 8 + qid * 2;
            const float b0 = bias[n0], b1 = bias[n0 + 1];
            #pragma unroll
            for (int half = 0; half < 2; half++) {
                const int m = bm + wr * 32 + mt * 16 + grp + half * 8;
                const float v0 = acc[mt][na][2 * half + 0] + b0;
                const float v1 = acc[mt][na][2 * half + 1] + b1;
                const int b = m >> 11;
                const int sI = m & 2047;
                const int h = n0 >> 6;
                const int d = n0 & 63;
                const size_t o = ((((size_t)b * Hh + h) * Sq + sI) << 6) + d;
                *reinterpret_cast<__half2*>(&dst[o]) = __floats2half2_rn(v0, v1);
            }
        }
    }
}

// ---------------------------------------------------------------------------
// Output projection: fp32 row-major out
// ---------------------------------------------------------------------------
__global__ __launch_bounds__(256, 2)
void gemm_out(const __half* __restrict__ A, const __half* __restrict__ Bw,
              const float* __restrict__ bias, float* __restrict__ C)
{
    extern __shared__ char smem[];
    const uint32_t sb = smem_to_u32(smem);
    const int tid = threadIdx.x;
    const int wid = tid >> 5, lane = tid & 31;
    const int bm = blockIdx.y * TBM, bn = blockIdx.x * TBN;
    const int wr = wid & 3, wc = wid >> 2;

    float acc[2][8][4];
    #pragma unroll
    for (int a = 0; a < 2; a++)
        #pragma unroll
        for (int b = 0; b < 8; b++)
            #pragma unroll
            for (int c = 0; c < 4; c++) acc[a][b][c] = 0.f;

    gemm_mainloop(A, Bw, sb, tid, bm, bn, wr, wc, lane, acc);

    const int grp = lane >> 2, qid = lane & 3;
    #pragma unroll
    for (int mt = 0; mt < 2; mt++) {
        #pragma unroll
        for (int na = 0; na < 8; na++) {
            const int n0 = bn + wc * 64 + na * 8 + qid * 2;
            const float b0 = bias[n0], b1 = bias[n0 + 1];
            #pragma unroll
            for (int half = 0; half < 2; half++) {
                const int m = bm + wr * 32 + mt * 16 + grp + half * 8;
                *reinterpret_cast<float2*>(&C[(size_t)m * Dm + n0]) =
                    make_float2(acc[mt][na][2 * half + 0] + b0,
                                acc[mt][na][2 * half + 1] + b1);
            }
        }
    }
}

// ===========================================================================
// Tensor-core flash attention (fp16 QK^T + PV), K/V double-buffered.
// Output: fp16 row-major [b*s, Dm].
// ===========================================================================
constexpr int FBQ = 128, FBK = 64;
constexpr int FROWB = 144;                   // 64 fp16 = 128B + 16B pad
constexpr int F_Q   = 0;                     // 128*144 = 18432
constexpr int F_KV  = FBQ * FROWB;           // two 18432-byte stages
constexpr int KVSTG = 2 * FBK * FROWB;       // 18432 (K then V)
constexpr int FSMEM = F_KV + 2 * KVSTG;      // 55296

__global__ __launch_bounds__(256, 2)
void flash_tc(const __half* __restrict__ Qh, const __half* __restrict__ Kh,
              const __half* __restrict__ Vh, __half* __restrict__ Oh)
{
    extern __shared__ char smem[];
    const uint32_t sb = smem_to_u32(smem);
    const int tid = threadIdx.x;
    const int w = tid >> 5, lane = tid & 31;
    const int grp = lane >> 2, qid = lane & 3;

    const int bh = blockIdx.y;
    const int qt = gridDim.x - 1 - blockIdx.x;   // big tiles first
    const int q0 = qt * FBQ;
    const size_t rowbase = (size_t)bh * Sq;

    constexpr float SCALE = 0.18033688011112042f;  // (1/8) * log2(e)

    // load Q tile (group)
    #pragma unroll
    for (int i = 0; i < 4; i++) {
        int idx = tid + i * 256;
        int row = idx >> 3;
        int c = idx & 7;
        cp16(sb + F_Q + row * FROWB + c * 16,
             reinterpret_cast<const char*>(Qh + (rowbase + q0 + row) * Dh) + c * 16);
    }
    CP_COMMIT();

    // prefetch K/V tile 0 into stage 0
    auto issue_kv = [&](int k0, int stg) {
        const uint32_t base = sb + F_KV + stg * KVSTG;
        #pragma unroll
        for (int i = 0; i < 4; i++) {
            int idx = tid + i * 256;
            int arr = idx >> 9;            // 0=K 1=V
            int row = (idx >> 3) & 63;
            int c = idx & 7;
            const char* src = arr
                ? (const char*)(Vh + (rowbase + k0 + row) * Dh)
                : (const char*)(Kh + (rowbase + k0 + row) * Dh);
            cp16(base + arr * (FBK * FROWB) + row * FROWB + c * 16, src + c * 16);
        }
        CP_COMMIT();
    };
    issue_kv(0, 0);

    float m0 = -1e30f, m1 = -1e30f, l0 = 0.f, l1 = 0.f;
    float o[8][4];
    #pragma unroll
    for (int t = 0; t < 8; t++)
        #pragma unroll
        for (int i = 0; i < 4; i++) o[t][i] = 0.f;

    const int rw0 = q0 + w * 16;
    const uint32_t aOffQ = sb + F_Q + (w * 16 + lane % 16) * FROWB + (lane / 16) * 16;
    const uint32_t bOffK = (((lane >> 4) << 3) + (lane & 7)) * FROWB + ((lane >> 3) & 1) * 16;

    const int KT = 2 * (qt + 1);
    for (int kt = 0; kt < KT; kt++) {
        const int k0 = kt * FBK;
        const int s = kt & 1;
        if (kt + 1 < KT) { issue_kv((kt + 1) * FBK, s ^ 1); CP_WAIT1(); }
        else CP_WAIT0();
        __syncthreads();

        if (k0 <= rw0 + 15) {
            const uint32_t kbase = sb + F_KV + s * KVSTG;
            const uint32_t vbase = kbase + FBK * FROWB;

            // ---- S = Q K^T, fp16 ----
            float sc[8][4];
            #pragma unroll
            for (int t = 0; t < 8; t++)
                #pragma unroll
                for (int i = 0; i < 4; i++) sc[t][i] = 0.f;

            #pragma unroll
            for (int ks = 0; ks < 4; ks++) {
                uint32_t ah[4];
                ldsm4(ah, aOffQ + ks * 32);
                #pragma unroll
                for (int ntp = 0; ntp < 4; ntp++) {
                    uint32_t bhr[4];
                    ldsm4(bhr, kbase + ntp * 16 * FROWB + bOffK + ks * 32);
                    mma_f16(sc[2 * ntp + 0], ah, bhr[0], bhr[1]);
                    mma_f16(sc[2 * ntp + 1], ah, bhr[2], bhr[3]);
                }
            }

            const bool needMask = (k0 + FBK - 1 > rw0);
            const int r0g = rw0 + grp, r1g = r0g + 8;
            #pragma unroll
            for (int t = 0; t < 8; t++) {
                #pragma unroll
                for (int i = 0; i < 4; i++) sc[t][i] *= SCALE;
                if (needMask) {
                    const int jc = k0 + t * 8 + qid * 2;
                    if (jc + 0 > r0g) sc[t][0] = -1e4f;
                    if (jc + 1 > r0g) sc[t][1] = -1e4f;
                    if (jc + 0 > r1g) sc[t][2] = -1e4f;
                    if (jc + 1 > r1g) sc[t][3] = -1e4f;
                }
            }

            float mx0 = sc[0][0], mx1 = sc[0][2];
            #pragma unroll
            for (int t = 0; t < 8; t++) {
                mx0 = fmaxf(mx0, fmaxf(sc[t][0], sc[t][1]));
                mx1 = fmaxf(mx1, fmaxf(sc[t][2], sc[t][3]));
            }
            mx0 = fmaxf(mx0, __shfl_xor_sync(0xffffffff, mx0, 1));
            mx0 = fmaxf(mx0, __shfl_xor_sync(0xffffffff, mx0, 2));
            mx1 = fmaxf(mx1, __shfl_xor_sync(0xffffffff, mx1, 1));
            mx1 = fmaxf(mx1, __shfl_xor_sync(0xffffffff, mx1, 2));
            const float nm0 = fmaxf(m0, mx0), nm1 = fmaxf(m1, mx1);
            const float f0 = exp2f(m0 - nm0), f1 = exp2f(m1 - nm1);
            m0 = nm0; m1 = nm1;

            uint32_t pp[8][2];
            float sum0 = 0.f, sum1 = 0.f;
            #pragma unroll
            for (int t = 0; t < 8; t++) {
                const float p0 = exp2f(sc[t][0] - m0);
                const float p1 = exp2f(sc[t][1] - m0);
                const float p2 = exp2f(sc[t][2] - m1);
                const float p3 = exp2f(sc[t][3] - m1);
                sum0 += p0 + p1; sum1 += p2 + p3;
                __half2 h01 = __floats2half2_rn(p0, p1);
                __half2 h23 = __floats2half2_rn(p2, p3);
                pp[t][0] = *reinterpret_cast<uint32_t*>(&h01);
                pp[t][1] = *reinterpret_cast<uint32_t*>(&h23);
            }
            sum0 += __shfl_xor_sync(0xffffffff, sum0, 1);
            sum0 += __shfl_xor_sync(0xffffffff, sum0, 2);
            sum1 += __shfl_xor_sync(0xffffffff, sum1, 1);
            sum1 += __shfl_xor_sync(0xffffffff, sum1, 2);
            l0 = l0 * f0 + sum0;
            l1 = l1 * f1 + sum1;

            #pragma unroll
            for (int t = 0; t < 8; t++) {
                o[t][0] *= f0; o[t][1] *= f0; o[t][2] *= f1; o[t][3] *= f1;
            }

            // ---- O += P * V ----
            #pragma unroll
            for (int kk = 0; kk < 4; kk++) {
                uint32_t a[4] = { pp[2 * kk][0], pp[2 * kk][1],
                                  pp[2 * kk + 1][0], pp[2 * kk + 1][1] };
                #pragma unroll
                for (int ntp = 0; ntp < 4; ntp++) {
                    uint32_t bv[4];
                    ldsm4t(bv, vbase + (kk * 16 + (lane & 15)) * FROWB
                               + (2 * ntp + (lane >> 4)) * 16);
                    mma_f16(o[2 * ntp + 0], a, bv[0], bv[1]);
                    mma_f16(o[2 * ntp + 1], a, bv[2], bv[3]);
                }
            }
        }
        __syncthreads();
    }

    // epilogue: fp16 row-major [b*s, Dm]
    const int b = bh >> 4, h = bh & 15;
    const float inv0 = 1.0f / l0, inv1 = 1.0f / l1;
    const size_t row0 = ((size_t)b * Sq + (q0 + w * 16 + grp)) * Dm + h * Dh;
    const size_t row1 = row0 + 8 * Dm;
    #pragma unroll
    for (int t = 0; t < 8; t++) {
        const int col = t * 8 + qid * 2;
        *reinterpret_cast<__half2*>(&Oh[row0 + col]) =
            __floats2half2_rn(o[t][0] * inv0, o[t][1] * inv0);
        *reinterpret_cast<__half2*>(&Oh[row1 + col]) =
            __floats2half2_rn(o[t][2] * inv1, o[t][3] * inv1);
    }
}

// ===========================================================================
extern "C" void kernel_launch(void* const* d_in, const int* in_sizes, int n_in,
                              void* d_out, int out_size)
{
    const float* x  = (const float*)d_in[0];
    const float* Wq = (const float*)d_in[2];
    const float* bq = (const float*)d_in[3];
    const float* Wk = (const float*)d_in[4];
    const float* bk = (const float*)d_in[5];
    const float* Wv = (const float*)d_in[6];
    const float* bv = (const float*)d_in[7];
    const float* Wo = (const float*)d_in[8];
    const float* bo = (const float*)d_in[9];
    float* out = (float*)d_out;

    __half *xh, *wptr, *qh, *kh, *vh;
    cudaGetSymbolAddress((void**)&xh, g_xh);
    cudaGetSymbolAddress((void**)&wptr, g_w);
    cudaGetSymbolAddress((void**)&qh, g_Qh);
    cudaGetSymbolAddress((void**)&kh, g_Kh);
    cudaGetSymbolAddress((void**)&vh, g_Vh);

    static bool attr_set = false;
    if (!attr_set) {
        cudaFuncSetAttribute(gemm_qkv, cudaFuncAttributeMaxDynamicSharedMemorySize, GSMEM);
        cudaFuncSetAttribute(gemm_out, cudaFuncAttributeMaxDynamicSharedMemorySize, GSMEM);
        cudaFuncSetAttribute(flash_tc, cudaFuncAttributeMaxDynamicSharedMemorySize, FSMEM);
        attr_set = true;
    }

    const size_t wN = (size_t)Dm * Dm;
    const int xn4 = Mr * Dm / 4;
    const int wn4 = (int)(wN / 4);

    cvt_f16<<<(xn4 + 255) / 256, 256>>>(x, xh, xn4);
    cvt_w4<<<dim3((wn4 + 255) / 256, 4), 256>>>(Wq, Wk, Wv, Wo, wptr, wn4);

    // fused QKV projection: N = 3072 packed
    gemm_qkv<<<dim3(3 * Dm / TBN, Mr / TBM), 256, GSMEM>>>(
        xh, wptr, bq, bk, bv, qh, kh, vh);

    // flash writes fp16 O over xh
    flash_tc<<<dim3(Sq / FBQ, Bz * Hh), 256, FSMEM>>>(qh, kh, vh, xh);

    // output projection
    gemm_out<<<dim3(Dm / TBN, Mr / TBM), 256, GSMEM>>>(xh, wptr + 3 * wN, bo, out);
}

// round 8
// speedup vs baseline: 7.8459x; 1.0360x over previous
#include <cuda_runtime.h>
#include <cuda_fp16.h>
#include <cstdint>
#include <math.h>

// Problem constants
constexpr int Bz = 4;
constexpr int Sq = 2048;
constexpr int Dm = 1024;
constexpr int Hh = 16;
constexpr int Dh = 64;
constexpr int Mr = Bz * Sq;    // 8192

// Scratch (allocation-free rule: __device__ globals)
__device__ __half g_xh[(size_t)Mr * Dm];      // x fp16; later reused for attn-out
__device__ __half g_w[4][(size_t)Dm * Dm];    // Wq, Wk, Wv, Wo fp16 (contiguous)
__device__ __half g_Qh[(size_t)Mr * Dm];
__device__ __half g_Kh[(size_t)Mr * Dm];
__device__ __half g_Vh[(size_t)Mr * Dm];

// ===========================================================================
// PTX helpers
// ===========================================================================
__device__ __forceinline__ uint32_t smem_to_u32(const void* p) {
    uint32_t a;
    asm("{ .reg .u64 t; cvta.to.shared.u64 t, %1; cvt.u32.u64 %0, t; }"
        : "=r"(a) : "l"(p));
    return a;
}
__device__ __forceinline__ void cp16(uint32_t dst, const void* src) {
    asm volatile("cp.async.cg.shared.global [%0], [%1], 16;" :: "r"(dst), "l"(src));
}
#define CP_COMMIT() asm volatile("cp.async.commit_group;" ::: "memory")
#define CP_WAIT1()  asm volatile("cp.async.wait_group 1;" ::: "memory")
#define CP_WAIT0()  asm volatile("cp.async.wait_group 0;" ::: "memory")

__device__ __forceinline__ void ldsm4(uint32_t* r, uint32_t addr) {
    asm volatile("ldmatrix.sync.aligned.m8n8.x4.shared.b16 {%0,%1,%2,%3}, [%4];"
        : "=r"(r[0]), "=r"(r[1]), "=r"(r[2]), "=r"(r[3]) : "r"(addr));
}
__device__ __forceinline__ void ldsm4t(uint32_t* r, uint32_t addr) {
    asm volatile("ldmatrix.sync.aligned.m8n8.x4.trans.shared.b16 {%0,%1,%2,%3}, [%4];"
        : "=r"(r[0]), "=r"(r[1]), "=r"(r[2]), "=r"(r[3]) : "r"(addr));
}
__device__ __forceinline__ void mma_f16(float* d, const uint32_t* a,
                                        uint32_t b0, uint32_t b1) {
    asm volatile(
        "mma.sync.aligned.m16n8k16.row.col.f32.f16.f16.f32 "
        "{%0,%1,%2,%3}, {%4,%5,%6,%7}, {%8,%9}, {%0,%1,%2,%3};"
        : "+f"(d[0]), "+f"(d[1]), "+f"(d[2]), "+f"(d[3])
        : "r"(a[0]), "r"(a[1]), "r"(a[2]), "r"(a[3]), "r"(b0), "r"(b1));
}
__device__ __forceinline__ uint32_t ex2_h2(uint32_t x) {
    uint32_t r;
    asm("ex2.approx.f16x2 %0, %1;" : "=r"(r) : "r"(x));
    return r;
}

// ===========================================================================
// Conversion kernels (pure bandwidth)
// ===========================================================================
__global__ __launch_bounds__(256)
void cvt_f16(const float* __restrict__ src, __half* __restrict__ dst, int n4)
{
    int i = blockIdx.x * blockDim.x + threadIdx.x;
    if (i >= n4) return;
    float4 v = reinterpret_cast<const float4*>(src)[i];
    reinterpret_cast<__half2*>(dst)[2 * i + 0] = __floats2half2_rn(v.x, v.y);
    reinterpret_cast<__half2*>(dst)[2 * i + 1] = __floats2half2_rn(v.z, v.w);
}

__global__ __launch_bounds__(256)
void cvt_w4(const float* __restrict__ w0, const float* __restrict__ w1,
            const float* __restrict__ w2, const float* __restrict__ w3,
            __half* __restrict__ dst, int n4)
{
    int i = blockIdx.x * blockDim.x + threadIdx.x;
    if (i >= n4) return;
    const float* srcs[4] = {w0, w1, w2, w3};
    const float* src = srcs[blockIdx.y];
    __half* d = dst + (size_t)blockIdx.y * n4 * 4;
    float4 v = reinterpret_cast<const float4*>(src)[i];
    reinterpret_cast<__half2*>(d)[2 * i + 0] = __floats2half2_rn(v.x, v.y);
    reinterpret_cast<__half2*>(d)[2 * i + 1] = __floats2half2_rn(v.z, v.w);
}

// ===========================================================================
// Shared GEMM pieces: 128x128x32 tiles, 8 warps, 3-stage cp.async ring
// ===========================================================================
constexpr int TBM = 128, TBN = 128, TKC = 32;
constexpr int ROWB  = 80;            // 32 fp16 = 64B + 16B pad
constexpr int TILEB = 128 * ROWB;    // 10240
constexpr int GSTG  = 2 * TILEB;     // A+B per stage
constexpr int GSMEM = 3 * GSTG;      // 61440

__device__ __forceinline__ void gemm_issue(
    const __half* A, const __half* B,
    uint32_t sb, int tid, int bm, int bn, int k0, int stage)
{
    #pragma unroll
    for (int i = 0; i < 4; i++) {
        int idx = tid + i * 256;
        int tile = idx >> 9;              // 0=A 1=B
        int row  = (idx >> 2) & 127;
        int c16  = idx & 3;
        const __half* src = tile ? B : A;
        int grow = (tile ? bn : bm) + row;
        const char* gsrc = reinterpret_cast<const char*>(src + (size_t)grow * Dm + k0)
                           + c16 * 16;
        uint32_t dst = sb + stage * GSTG + tile * TILEB + row * ROWB + c16 * 16;
        cp16(dst, gsrc);
    }
    CP_COMMIT();
}

// 3-stage mainloop: wait -> sync -> prefetch(ck+2) -> compute(ck)
__device__ __forceinline__ void gemm_mainloop(
    const __half* A, const __half* B, uint32_t sb, int tid,
    int bm, int bn, int wr, int wc, int lane, float acc[2][8][4])
{
    const uint32_t aOff = (lane % 16) * ROWB + (lane / 16) * 16;
    const uint32_t bOff = (((lane >> 4) << 3) + (lane & 7)) * ROWB + ((lane >> 3) & 1) * 16;

    gemm_issue(A, B, sb, tid, bm, bn, 0, 0);
    gemm_issue(A, B, sb, tid, bm, bn, TKC, 1);

    const int NCK = Dm / TKC;    // 32
    int stage = 0;
    for (int ck = 0; ck < NCK; ck++) {
        if (ck + 1 < NCK) { CP_WAIT1(); } else { CP_WAIT0(); }
        __syncthreads();
        if (ck + 2 < NCK) {
            int st2 = stage + 2; if (st2 >= 3) st2 -= 3;
            gemm_issue(A, B, sb, tid, bm, bn, (ck + 2) * TKC, st2);
        }

        const uint32_t stg = sb + stage * GSTG;
        const uint32_t aB  = stg + (wr * 32) * ROWB + aOff;
        const uint32_t bB  = stg + TILEB + (wc * 64) * ROWB + bOff;

        #pragma unroll
        for (int ks = 0; ks < 2; ks++) {
            uint32_t ah[2][4];
            #pragma unroll
            for (int mt = 0; mt < 2; mt++)
                ldsm4(ah[mt], aB + mt * 16 * ROWB + ks * 32);
            #pragma unroll
            for (int nt = 0; nt < 4; nt++) {
                uint32_t bh[4];
                ldsm4(bh, bB + nt * 16 * ROWB + ks * 32);
                #pragma unroll
                for (int mt = 0; mt < 2; mt++) {
                    mma_f16(acc[mt][2 * nt + 0], ah[mt], bh[0], bh[1]);
                    mma_f16(acc[mt][2 * nt + 1], ah[mt], bh[2], bh[3]);
                }
            }
        }
        if (++stage == 3) stage = 0;
    }
}

// ---------------------------------------------------------------------------
// Fused QKV projection: B = packed [Wq;Wk;Wv] (3072 rows). fp16 scatter.
// ---------------------------------------------------------------------------
__global__ __launch_bounds__(256, 2)
void gemm_qkv(const __half* __restrict__ A, const __half* __restrict__ Bw,
              const float* __restrict__ bq, const float* __restrict__ bk,
              const float* __restrict__ bv,
              __half* __restrict__ Qh, __half* __restrict__ Kh,
              __half* __restrict__ Vh)
{
    extern __shared__ char smem[];
    const uint32_t sb = smem_to_u32(smem);
    const int tid = threadIdx.x;
    const int wid = tid >> 5, lane = tid & 31;
    const int bm = blockIdx.y * TBM, bn = blockIdx.x * TBN;   // bn in [0,3072)
    const int wr = wid & 3, wc = wid >> 2;

    float acc[2][8][4];
    #pragma unroll
    for (int a = 0; a < 2; a++)
        #pragma unroll
        for (int b = 0; b < 8; b++)
            #pragma unroll
            for (int c = 0; c < 4; c++) acc[a][b][c] = 0.f;

    gemm_mainloop(A, Bw, sb, tid, bm, bn, wr, wc, lane, acc);

    const int sel = bn >> 10;
    const int bnl = bn & 1023;
    const float* bias = (sel == 0) ? bq : (sel == 1) ? bk : bv;
    __half* dst = (sel == 0) ? Qh : (sel == 1) ? Kh : Vh;

    const int grp = lane >> 2, qid = lane & 3;
    #pragma unroll
    for (int mt = 0; mt < 2; mt++) {
        #pragma unroll
        for (int na = 0; na < 8; na++) {
            const int n0 = bnl + wc * 64 + na * 8 + qid * 2;
            const float b0 = bias[n0], b1 = bias[n0 + 1];
            #pragma unroll
            for (int half = 0; half < 2; half++) {
                const int m = bm + wr * 32 + mt * 16 + grp + half * 8;
                const float v0 = acc[mt][na][2 * half + 0] + b0;
                const float v1 = acc[mt][na][2 * half + 1] + b1;
                const int b = m >> 11;
                const int sI = m & 2047;
                const int h = n0 >> 6;
                const int d = n0 & 63;
                const size_t o = ((((size_t)b * Hh + h) * Sq + sI) << 6) + d;
                *reinterpret_cast<__half2*>(&dst[o]) = __floats2half2_rn(v0, v1);
            }
        }
    }
}

// ---------------------------------------------------------------------------
// Output projection: fp32 row-major out
// ---------------------------------------------------------------------------
__global__ __launch_bounds__(256, 2)
void gemm_out(const __half* __restrict__ A, const __half* __restrict__ Bw,
              const float* __restrict__ bias, float* __restrict__ C)
{
    extern __shared__ char smem[];
    const uint32_t sb = smem_to_u32(smem);
    const int tid = threadIdx.x;
    const int wid = tid >> 5, lane = tid & 31;
    const int bm = blockIdx.y * TBM, bn = blockIdx.x * TBN;
    const int wr = wid & 3, wc = wid >> 2;

    float acc[2][8][4];
    #pragma unroll
    for (int a = 0; a < 2; a++)
        #pragma unroll
        for (int b = 0; b < 8; b++)
            #pragma unroll
            for (int c = 0; c < 4; c++) acc[a][b][c] = 0.f;

    gemm_mainloop(A, Bw, sb, tid, bm, bn, wr, wc, lane, acc);

    const int grp = lane >> 2, qid = lane & 3;
    #pragma unroll
    for (int mt = 0; mt < 2; mt++) {
        #pragma unroll
        for (int na = 0; na < 8; na++) {
            const int n0 = bn + wc * 64 + na * 8 + qid * 2;
            const float b0 = bias[n0], b1 = bias[n0 + 1];
            #pragma unroll
            for (int half = 0; half < 2; half++) {
                const int m = bm + wr * 32 + mt * 16 + grp + half * 8;
                *reinterpret_cast<float2*>(&C[(size_t)m * Dm + n0]) =
                    make_float2(acc[mt][na][2 * half + 0] + b0,
                                acc[mt][na][2 * half + 1] + b1);
            }
        }
    }
}

// ===========================================================================
// Tensor-core flash attention (fp16 QK^T + PV), 3-stage K/V ring,
// f16x2 exp, row sums via MMA-with-ones. Output fp16 row-major [b*s, Dm].
// ===========================================================================
constexpr int FBQ = 128, FBK = 64;
constexpr int FROWB = 144;                   // 64 fp16 = 128B + 16B pad
constexpr int F_Q   = 0;                     // 128*144 = 18432
constexpr int F_KV  = FBQ * FROWB;
constexpr int KVSTG = 2 * FBK * FROWB;       // 18432 (K then V)
constexpr int FSMEM = F_KV + 3 * KVSTG;      // 73728

__global__ __launch_bounds__(256, 2)
void flash_tc(const __half* __restrict__ Qh, const __half* __restrict__ Kh,
              const __half* __restrict__ Vh, __half* __restrict__ Oh)
{
    extern __shared__ char smem[];
    const uint32_t sb = smem_to_u32(smem);
    const int tid = threadIdx.x;
    const int w = tid >> 5, lane = tid & 31;
    const int grp = lane >> 2, qid = lane & 3;

    const int bh = blockIdx.y;
    const int qt = gridDim.x - 1 - blockIdx.x;   // big tiles first
    const int q0 = qt * FBQ;
    const size_t rowbase = (size_t)bh * Sq;

    constexpr float SCALE = 0.18033688011112042f;  // (1/8) * log2(e)
    constexpr uint32_t ONE2 = 0x3C003C00;          // (1.0h, 1.0h)

    // load Q tile (own commit group)
    #pragma unroll
    for (int i = 0; i < 4; i++) {
        int idx = tid + i * 256;
        int row = idx >> 3;
        int c = idx & 7;
        cp16(sb + F_Q + row * FROWB + c * 16,
             reinterpret_cast<const char*>(Qh + (rowbase + q0 + row) * Dh) + c * 16);
    }
    CP_COMMIT();

    auto issue_kv = [&](int k0, int stg) {
        const uint32_t base = sb + F_KV + stg * KVSTG;
        #pragma unroll
        for (int i = 0; i < 4; i++) {
            int idx = tid + i * 256;
            int arr = idx >> 9;            // 0=K 1=V
            int row = (idx >> 3) & 63;
            int c = idx & 7;
            const char* src = arr
                ? (const char*)(Vh + (rowbase + k0 + row) * Dh)
                : (const char*)(Kh + (rowbase + k0 + row) * Dh);
            cp16(base + arr * (FBK * FROWB) + row * FROWB + c * 16, src + c * 16);
        }
        CP_COMMIT();
    };

    const int KT = 2 * (qt + 1);
    issue_kv(0, 0);
    if (KT > 1) issue_kv(FBK, 1);

    float m0 = -1e30f, m1 = -1e30f;
    float o[8][4], ls[4];
    #pragma unroll
    for (int t = 0; t < 8; t++)
        #pragma unroll
        for (int i = 0; i < 4; i++) o[t][i] = 0.f;
    #pragma unroll
    for (int i = 0; i < 4; i++) ls[i] = 0.f;

    const int rw0 = q0 + w * 16;
    const uint32_t aOffQ = sb + F_Q + (w * 16 + lane % 16) * FROWB + (lane / 16) * 16;
    const uint32_t bOffK = (((lane >> 4) << 3) + (lane & 7)) * FROWB + ((lane >> 3) & 1) * 16;

    int stage = 0;
    for (int kt = 0; kt < KT; kt++) {
        const int k0 = kt * FBK;
        if (kt + 1 < KT) { CP_WAIT1(); } else { CP_WAIT0(); }
        __syncthreads();
        if (kt + 2 < KT) {
            int st2 = stage + 2; if (st2 >= 3) st2 -= 3;
            issue_kv((kt + 2) * FBK, st2);
        }

        if (k0 <= rw0 + 15) {
            const uint32_t kbase = sb + F_KV + stage * KVSTG;
            const uint32_t vbase = kbase + FBK * FROWB;

            // ---- S = Q K^T, fp16 ----
            float sc[8][4];
            #pragma unroll
            for (int t = 0; t < 8; t++)
                #pragma unroll
                for (int i = 0; i < 4; i++) sc[t][i] = 0.f;

            #pragma unroll
            for (int ks = 0; ks < 4; ks++) {
                uint32_t ah[4];
                ldsm4(ah, aOffQ + ks * 32);
                #pragma unroll
                for (int ntp = 0; ntp < 4; ntp++) {
                    uint32_t bhr[4];
                    ldsm4(bhr, kbase + ntp * 16 * FROWB + bOffK + ks * 32);
                    mma_f16(sc[2 * ntp + 0], ah, bhr[0], bhr[1]);
                    mma_f16(sc[2 * ntp + 1], ah, bhr[2], bhr[3]);
                }
            }

            const bool needMask = (k0 + FBK - 1 > rw0);
            const int r0g = rw0 + grp, r1g = r0g + 8;
            #pragma unroll
            for (int t = 0; t < 8; t++) {
                #pragma unroll
                for (int i = 0; i < 4; i++) sc[t][i] *= SCALE;
                if (needMask) {
                    const int jc = k0 + t * 8 + qid * 2;
                    if (jc + 0 > r0g) sc[t][0] = -1e4f;
                    if (jc + 1 > r0g) sc[t][1] = -1e4f;
                    if (jc + 0 > r1g) sc[t][2] = -1e4f;
                    if (jc + 1 > r1g) sc[t][3] = -1e4f;
                }
            }

            // ---- online softmax ----
            float mx0 = sc[0][0], mx1 = sc[0][2];
            #pragma unroll
            for (int t = 0; t < 8; t++) {
                mx0 = fmaxf(mx0, fmaxf(sc[t][0], sc[t][1]));
                mx1 = fmaxf(mx1, fmaxf(sc[t][2], sc[t][3]));
            }
            mx0 = fmaxf(mx0, __shfl_xor_sync(0xffffffff, mx0, 1));
            mx0 = fmaxf(mx0, __shfl_xor_sync(0xffffffff, mx0, 2));
            mx1 = fmaxf(mx1, __shfl_xor_sync(0xffffffff, mx1, 1));
            mx1 = fmaxf(mx1, __shfl_xor_sync(0xffffffff, mx1, 2));
            const float nm0 = fmaxf(m0, mx0), nm1 = fmaxf(m1, mx1);
            const float f0 = exp2f(m0 - nm0), f1 = exp2f(m1 - nm1);
            m0 = nm0; m1 = nm1;

            // P = 2^(sc - m) computed in f16x2 (lands directly in MMA layout)
            uint32_t pp[8][2];
            #pragma unroll
            for (int t = 0; t < 8; t++) {
                __half2 h01 = __floats2half2_rn(sc[t][0] - m0, sc[t][1] - m0);
                __half2 h23 = __floats2half2_rn(sc[t][2] - m1, sc[t][3] - m1);
                pp[t][0] = ex2_h2(*reinterpret_cast<uint32_t*>(&h01));
                pp[t][1] = ex2_h2(*reinterpret_cast<uint32_t*>(&h23));
            }

            // rescale O and row-sum accumulators
            #pragma unroll
            for (int t = 0; t < 8; t++) {
                o[t][0] *= f0; o[t][1] *= f0; o[t][2] *= f1; o[t][3] *= f1;
            }
            ls[0] *= f0; ls[1] *= f0; ls[2] *= f1; ls[3] *= f1;

            // ---- O += P * V ; ls += P * ones ----
            #pragma unroll
            for (int kk = 0; kk < 4; kk++) {
                uint32_t a[4] = { pp[2 * kk][0], pp[2 * kk][1],
                                  pp[2 * kk + 1][0], pp[2 * kk + 1][1] };
                mma_f16(ls, a, ONE2, ONE2);
                #pragma unroll
                for (int ntp = 0; ntp < 4; ntp++) {
                    uint32_t bv[4];
                    ldsm4t(bv, vbase + (kk * 16 + (lane & 15)) * FROWB
                               + (2 * ntp + (lane >> 4)) * 16);
                    mma_f16(o[2 * ntp + 0], a, bv[0], bv[1]);
                    mma_f16(o[2 * ntp + 1], a, bv[2], bv[3]);
                }
            }
        }
        if (++stage == 3) stage = 0;
    }

    // epilogue: fp16 row-major [b*s, Dm]
    const int b = bh >> 4, h = bh & 15;
    const float inv0 = 1.0f / ls[0], inv1 = 1.0f / ls[2];
    const size_t row0 = ((size_t)b * Sq + (q0 + w * 16 + grp)) * Dm + h * Dh;
    const size_t row1 = row0 + 8 * Dm;
    #pragma unroll
    for (int t = 0; t < 8; t++) {
        const int col = t * 8 + qid * 2;
        *reinterpret_cast<__half2*>(&Oh[row0 + col]) =
            __floats2half2_rn(o[t][0] * inv0, o[t][1] * inv0);
        *reinterpret_cast<__half2*>(&Oh[row1 + col]) =
            __floats2half2_rn(o[t][2] * inv1, o[t][3] * inv1);
    }
}

// ===========================================================================
extern "C" void kernel_launch(void* const* d_in, const int* in_sizes, int n_in,
                              void* d_out, int out_size)
{
    const float* x  = (const float*)d_in[0];
    const float* Wq = (const float*)d_in[2];
    const float* bq = (const float*)d_in[3];
    const float* Wk = (const float*)d_in[4];
    const float* bk = (const float*)d_in[5];
    const float* Wv = (const float*)d_in[6];
    const float* bv = (const float*)d_in[7];
    const float* Wo = (const float*)d_in[8];
    const float* bo = (const float*)d_in[9];
    float* out = (float*)d_out;

    __half *xh, *wptr, *qh, *kh, *vh;
    cudaGetSymbolAddress((void**)&xh, g_xh);
    cudaGetSymbolAddress((void**)&wptr, g_w);
    cudaGetSymbolAddress((void**)&qh, g_Qh);
    cudaGetSymbolAddress((void**)&kh, g_Kh);
    cudaGetSymbolAddress((void**)&vh, g_Vh);

    static bool attr_set = false;
    if (!attr_set) {
        cudaFuncSetAttribute(gemm_qkv, cudaFuncAttributeMaxDynamicSharedMemorySize, GSMEM);
        cudaFuncSetAttribute(gemm_out, cudaFuncAttributeMaxDynamicSharedMemorySize, GSMEM);
        cudaFuncSetAttribute(flash_tc, cudaFuncAttributeMaxDynamicSharedMemorySize, FSMEM);
        attr_set = true;
    }

    const size_t wN = (size_t)Dm * Dm;
    const int xn4 = Mr * Dm / 4;
    const int wn4 = (int)(wN / 4);

    cvt_f16<<<(xn4 + 255) / 256, 256>>>(x, xh, xn4);
    cvt_w4<<<dim3((wn4 + 255) / 256, 4), 256>>>(Wq, Wk, Wv, Wo, wptr, wn4);

    gemm_qkv<<<dim3(3 * Dm / TBN, Mr / TBM), 256, GSMEM>>>(
        xh, wptr, bq, bk, bv, qh, kh, vh);

    flash_tc<<<dim3(Sq / FBQ, Bz * Hh), 256, FSMEM>>>(qh, kh, vh, xh);

    gemm_out<<<dim3(Dm / TBN, Mr / TBM), 256, GSMEM>>>(xh, wptr + 3 * wN, bo, out);
}